// round 1
// baseline (speedup 1.0000x reference)
#include <cuda_runtime.h>
#include <cuda_bf16.h>
#include <math.h>

// ---------------------------------------------------------------------------
// Wav2VecFeats: conv stack (k,s) = (10,5),(3,2),(3,2),(3,2),(3,2),(2,2),(2,2)
// B=8, L=40000, C=512, PROJ=256, HID=128, NCLS=5, N_WORDS=64
// Seq lens: 40000 ->7999 ->3999 ->1999 ->999 ->499 ->249 ->124
// ---------------------------------------------------------------------------

#define BB 8
#define CC 512
#define L0 40000
#define T0 7999
#define T1 3999
#define T2 1999
#define T3 999
#define T4 499
#define T5 249
#define T6 124

// Scratch (static device arrays; no runtime allocation allowed)
__device__ float g_bufA[BB * CC * T0];  // ~131 MB
__device__ float g_bufB[BB * CC * T1];  // ~65 MB

__device__ __forceinline__ float gelu_tanh(float x) {
    const float c0 = 0.7978845608028654f;   // sqrt(2/pi)
    const float c1 = 0.044715f;
    float x3 = x * x * x;
    float t = tanhf(c0 * (x + c1 * x3));
    return 0.5f * x * (1.0f + t);
}

// ---------------------------------------------------------------------------
// conv0: in (B, 40000) -> out (B, 512, 7999), k=10, s=5, single input channel.
// Writes RAW output (norm+gelu applied later).
// ---------------------------------------------------------------------------
#define C0_TT 128
__global__ __launch_bounds__(256) void conv0_kernel(
    const float* __restrict__ x, const float* __restrict__ w,
    float* __restrict__ out)
{
    __shared__ float sx[5 * C0_TT + 10];          // 650
    __shared__ float sw[CC * 10];                 // 5120
    const int b = blockIdx.y;
    const int t0 = blockIdx.x * C0_TT;
    const int tid = threadIdx.x;

    for (int i = tid; i < CC * 10; i += 256) sw[i] = w[i];
    for (int i = tid; i < 5 * C0_TT + 10; i += 256) {
        int gi = 5 * t0 + i;
        sx[i] = (gi < L0) ? x[b * L0 + gi] : 0.0f;
    }
    __syncthreads();

    for (int idx = tid; idx < CC * C0_TT; idx += 256) {
        int tl = idx & (C0_TT - 1);
        int c  = idx >> 7;                         // C0_TT == 128
        int t  = t0 + tl;
        if (t < T0) {
            float acc = 0.0f;
            const float* wc = &sw[c * 10];
            const float* xp = &sx[5 * tl];
            #pragma unroll
            for (int j = 0; j < 10; ++j) acc = fmaf(wc[j], xp[j], acc);
            out[(b * CC + c) * T0 + t] = acc;
        }
    }
}

// ---------------------------------------------------------------------------
// Per-(b,c) normalization over time (mean/var, population) + affine + gelu.
// grid = (C, B), 256 threads. In-place on g_bufA.
// ---------------------------------------------------------------------------
__global__ __launch_bounds__(256) void gn_gelu_kernel(
    float* __restrict__ h, const float* __restrict__ scale,
    const float* __restrict__ bias)
{
    const int c = blockIdx.x;
    const int b = blockIdx.y;
    const int tid = threadIdx.x;
    float* p = h + (size_t)(b * CC + c) * T0;

    float s = 0.0f, s2 = 0.0f;
    for (int i = tid; i < T0; i += 256) {
        float v = p[i];
        s += v; s2 += v * v;
    }
    // warp reduce
    #pragma unroll
    for (int off = 16; off > 0; off >>= 1) {
        s  += __shfl_down_sync(0xffffffffu, s,  off);
        s2 += __shfl_down_sync(0xffffffffu, s2, off);
    }
    __shared__ float ws[8], ws2[8];
    int wid = tid >> 5, lid = tid & 31;
    if (lid == 0) { ws[wid] = s; ws2[wid] = s2; }
    __syncthreads();
    if (tid == 0) {
        float S = 0.0f, S2 = 0.0f;
        #pragma unroll
        for (int i = 0; i < 8; ++i) { S += ws[i]; S2 += ws2[i]; }
        ws[0] = S; ws2[0] = S2;
    }
    __syncthreads();
    float mean = ws[0] * (1.0f / T0);
    float var  = ws2[0] * (1.0f / T0) - mean * mean;
    float inv  = rsqrtf(var + 1e-5f);
    float a = scale[c] * inv;
    float d = bias[c] - mean * a;
    for (int i = tid; i < T0; i += 256) {
        p[i] = gelu_tanh(fmaf(p[i], a, d));
    }
}

// ---------------------------------------------------------------------------
// Generic dense conv layer: in (B, 512, Tin), w (512, 512, K), stride 2,
// out (B, 512, Tout) with fused gelu. GEMM-style tiling:
//   block tile = COT x TT (co x t), register tile = OPC x OPT per thread.
//   COT = 16*OPC, TT = 16*OPT, 256 threads (16x16).
// ---------------------------------------------------------------------------
template<int K, int OPC, int OPT>
__global__ __launch_bounds__(256, 2) void conv_kernel(
    const float* __restrict__ in, const float* __restrict__ w,
    float* __restrict__ out, int Tin, int Tout)
{
    constexpr int COT = 16 * OPC;
    constexpr int TT  = 16 * OPT;
    constexpr int CIT = 8;
    constexpr int IN_W = 2 * TT + K - 1;
    constexpr int WROW = CIT * K + 1;             // padded

    __shared__ float sIn[CIT][IN_W];
    __shared__ float sW[COT][WROW];

    const int b   = blockIdx.z;
    const int co0 = blockIdx.y * COT;
    const int t0  = blockIdx.x * TT;
    const int tid = threadIdx.x;
    const int tx  = tid & 15;
    const int ty  = tid >> 4;

    const float* inb = in + (size_t)b * CC * Tin;

    float acc[OPC][OPT];
    #pragma unroll
    for (int o = 0; o < OPC; ++o)
        #pragma unroll
        for (int i = 0; i < OPT; ++i) acc[o][i] = 0.0f;

    for (int ci0 = 0; ci0 < CC; ci0 += CIT) {
        // load weight tile: COT x CIT x K
        for (int i = tid; i < COT * CIT * K; i += 256) {
            int co = i / (CIT * K);
            int r  = i - co * (CIT * K);           // r = ci*K + j
            sW[co][r] = w[(size_t)(co0 + co) * (CC * K) + ci0 * K + r];
        }
        // load input tile: CIT x IN_W
        for (int i = tid; i < CIT * IN_W; i += 256) {
            int ci = i / IN_W;
            int p  = i - ci * IN_W;
            int gp = 2 * t0 + p;
            sIn[ci][p] = (gp < Tin) ? inb[(size_t)(ci0 + ci) * Tin + gp] : 0.0f;
        }
        __syncthreads();

        #pragma unroll
        for (int ci = 0; ci < CIT; ++ci) {
            #pragma unroll
            for (int j = 0; j < K; ++j) {
                float av[OPT], bv[OPC];
                #pragma unroll
                for (int i = 0; i < OPT; ++i)
                    av[i] = sIn[ci][2 * (tx + 16 * i) + j];
                #pragma unroll
                for (int o = 0; o < OPC; ++o)
                    bv[o] = sW[ty + 16 * o][ci * K + j];
                #pragma unroll
                for (int o = 0; o < OPC; ++o)
                    #pragma unroll
                    for (int i = 0; i < OPT; ++i)
                        acc[o][i] = fmaf(bv[o], av[i], acc[o][i]);
            }
        }
        __syncthreads();
    }

    #pragma unroll
    for (int o = 0; o < OPC; ++o) {
        int co = co0 + ty + 16 * o;
        #pragma unroll
        for (int i = 0; i < OPT; ++i) {
            int t = t0 + tx + 16 * i;
            if (t < Tout)
                out[((size_t)b * CC + co) * Tout + t] = gelu_tanh(acc[o][i]);
        }
    }
}

// ---------------------------------------------------------------------------
// Tail: time-mean -> proj(512->256)+relu -> gather word head:
//   h1 = relu(feat @ w1[wid] + b1[wid]) (256->128); out = h1 @ w2[wid] + b2[wid]
// One block per batch element, 256 threads.
// ---------------------------------------------------------------------------
__global__ __launch_bounds__(256) void tail_kernel(
    const float* __restrict__ h, const int* __restrict__ word_ids,
    const float* __restrict__ proj_w, const float* __restrict__ proj_b,
    const float* __restrict__ cls_w1, const float* __restrict__ cls_b1,
    const float* __restrict__ cls_w2, const float* __restrict__ cls_b2,
    float* __restrict__ out)
{
    const int b = blockIdx.x;
    const int tid = threadIdx.x;
    __shared__ float feat[CC];
    __shared__ float pr[256];
    __shared__ float h1[128];

    const float* hb = h + (size_t)b * CC * T6;
    for (int c = tid; c < CC; c += 256) {
        float s = 0.0f;
        const float* row = hb + (size_t)c * T6;
        for (int t = 0; t < T6; ++t) s += row[t];
        feat[c] = s * (1.0f / (float)T6);
    }
    __syncthreads();

    {   // proj: 256 outputs, one per thread
        float s = proj_b[tid];
        const float* wr = proj_w + (size_t)tid * CC;
        for (int d = 0; d < CC; ++d) s = fmaf(wr[d], feat[d], s);
        pr[tid] = fmaxf(s, 0.0f);
    }
    __syncthreads();

    const int wid = word_ids[b];
    if (tid < 128) {
        float s = cls_b1[wid * 128 + tid];
        const float* w1 = cls_w1 + (size_t)wid * 256 * 128;
        for (int d = 0; d < 256; ++d)
            s = fmaf(pr[d], w1[d * 128 + tid], s);
        h1[tid] = fmaxf(s, 0.0f);
    }
    __syncthreads();

    if (tid < 5) {
        float s = cls_b2[wid * 5 + tid];
        const float* w2 = cls_w2 + (size_t)wid * 128 * 5;
        for (int d = 0; d < 128; ++d)
            s = fmaf(h1[d], w2[d * 5 + tid], s);
        out[b * 5 + tid] = s;
    }
}

// ---------------------------------------------------------------------------
// Launch
// ---------------------------------------------------------------------------
extern "C" void kernel_launch(void* const* d_in, const int* in_sizes, int n_in,
                              void* d_out, int out_size)
{
    const float* x        = (const float*)d_in[0];
    const int*   word_ids = (const int*)  d_in[1];
    const float* gn_scale = (const float*)d_in[2];
    const float* gn_bias  = (const float*)d_in[3];
    const float* proj_w   = (const float*)d_in[4];
    const float* proj_b   = (const float*)d_in[5];
    const float* cls_w1   = (const float*)d_in[6];
    const float* cls_b1   = (const float*)d_in[7];
    const float* cls_w2   = (const float*)d_in[8];
    const float* cls_b2   = (const float*)d_in[9];
    const float* w0       = (const float*)d_in[10];
    const float* w1       = (const float*)d_in[11];
    const float* w2       = (const float*)d_in[12];
    const float* w3       = (const float*)d_in[13];
    const float* w4       = (const float*)d_in[14];
    const float* w5       = (const float*)d_in[15];
    const float* w6       = (const float*)d_in[16];
    float* out = (float*)d_out;

    float *bufA = nullptr, *bufB = nullptr;
    cudaGetSymbolAddress((void**)&bufA, g_bufA);
    cudaGetSymbolAddress((void**)&bufB, g_bufB);

    // conv0 (raw) -> A
    conv0_kernel<<<dim3((T0 + C0_TT - 1) / C0_TT, BB), 256>>>(x, w0, bufA);
    // norm + gelu in-place on A
    gn_gelu_kernel<<<dim3(CC, BB), 256>>>(bufA, gn_scale, gn_bias);

    // conv1..4: k=3, tile 128co x 128t
    conv_kernel<3, 8, 8><<<dim3((T1 + 127) / 128, CC / 128, BB), 256>>>(bufA, w1, bufB, T0, T1);
    conv_kernel<3, 8, 8><<<dim3((T2 + 127) / 128, CC / 128, BB), 256>>>(bufB, w2, bufA, T1, T2);
    conv_kernel<3, 8, 8><<<dim3((T3 + 127) / 128, CC / 128, BB), 256>>>(bufA, w3, bufB, T2, T3);
    conv_kernel<3, 8, 8><<<dim3((T4 + 127) / 128, CC / 128, BB), 256>>>(bufB, w4, bufA, T3, T4);
    // conv5: k=2, tile 64 x 64
    conv_kernel<2, 4, 4><<<dim3((T5 + 63) / 64, CC / 64, BB), 256>>>(bufA, w5, bufB, T4, T5);
    // conv6: k=2, tile 64 x 32
    conv_kernel<2, 4, 2><<<dim3((T6 + 31) / 32, CC / 64, BB), 256>>>(bufB, w6, bufA, T5, T6);

    // tail
    tail_kernel<<<BB, 256>>>(bufA, word_ids, proj_w, proj_b,
                             cls_w1, cls_b1, cls_w2, cls_b2, out);
}

// round 2
// speedup vs baseline: 1.1813x; 1.1813x over previous
#include <cuda_runtime.h>
#include <cuda_bf16.h>
#include <math.h>

// ---------------------------------------------------------------------------
// Wav2VecFeats: conv stack (k,s) = (10,5),(3,2),(3,2),(3,2),(3,2),(2,2),(2,2)
// B=8, L=40000, C=512, PROJ=256, HID=128, NCLS=5, N_WORDS=64
// Seq lens: 40000 ->7999 ->3999 ->1999 ->999 ->499 ->249 ->124
// R1: packed fp32x2 FMA (FFMA2) inner loop — 2 exact fp32 MACs per issue slot.
// ---------------------------------------------------------------------------

#define BB 8
#define CC 512
#define L0 40000
#define T0 7999
#define T1 3999
#define T2 1999
#define T3 999
#define T4 499
#define T5 249
#define T6 124

typedef unsigned long long u64;

// Scratch (static device arrays; no runtime allocation allowed)
__device__ float g_bufA[BB * CC * T0];  // ~131 MB
__device__ float g_bufB[BB * CC * T1];  // ~65 MB

__device__ __forceinline__ float gelu_tanh(float x) {
    const float c0 = 0.7978845608028654f;   // sqrt(2/pi)
    const float c1 = 0.044715f;
    float x3 = x * x * x;
    float t = tanhf(c0 * (x + c1 * x3));
    return 0.5f * x * (1.0f + t);
}

// --- packed f32x2 helpers (Blackwell) --------------------------------------
__device__ __forceinline__ u64 pack2bcast(float x) {
    u64 r;
    asm("mov.b64 %0, {%1, %1};" : "=l"(r) : "f"(x));
    return r;
}
__device__ __forceinline__ void fma2(u64& d, u64 a, u64 b) {
    asm("fma.rn.f32x2 %0, %1, %2, %0;" : "+l"(d) : "l"(a), "l"(b));
}
__device__ __forceinline__ void unpack2(u64 v, float& lo, float& hi) {
    asm("mov.b64 {%0, %1}, %2;" : "=f"(lo), "=f"(hi) : "l"(v));
}

// ---------------------------------------------------------------------------
// conv0: in (B, 40000) -> out (B, 512, 7999), k=10, s=5, single input channel.
// ---------------------------------------------------------------------------
#define C0_TT 128
__global__ __launch_bounds__(256) void conv0_kernel(
    const float* __restrict__ x, const float* __restrict__ w,
    float* __restrict__ out)
{
    __shared__ float sx[5 * C0_TT + 10];
    __shared__ float sw[CC * 10];
    const int b = blockIdx.y;
    const int t0 = blockIdx.x * C0_TT;
    const int tid = threadIdx.x;

    for (int i = tid; i < CC * 10; i += 256) sw[i] = w[i];
    for (int i = tid; i < 5 * C0_TT + 10; i += 256) {
        int gi = 5 * t0 + i;
        sx[i] = (gi < L0) ? x[b * L0 + gi] : 0.0f;
    }
    __syncthreads();

    for (int idx = tid; idx < CC * C0_TT; idx += 256) {
        int tl = idx & (C0_TT - 1);
        int c  = idx >> 7;
        int t  = t0 + tl;
        if (t < T0) {
            float acc = 0.0f;
            const float* wc = &sw[c * 10];
            const float* xp = &sx[5 * tl];
            #pragma unroll
            for (int j = 0; j < 10; ++j) acc = fmaf(wc[j], xp[j], acc);
            out[(b * CC + c) * T0 + t] = acc;
        }
    }
}

// ---------------------------------------------------------------------------
// Per-(b,c) normalization over time + affine + gelu (in-place).
// ---------------------------------------------------------------------------
__global__ __launch_bounds__(256) void gn_gelu_kernel(
    float* __restrict__ h, const float* __restrict__ scale,
    const float* __restrict__ bias)
{
    const int c = blockIdx.x;
    const int b = blockIdx.y;
    const int tid = threadIdx.x;
    float* p = h + (size_t)(b * CC + c) * T0;

    float s = 0.0f, s2 = 0.0f;
    for (int i = tid; i < T0; i += 256) {
        float v = p[i];
        s += v; s2 += v * v;
    }
    #pragma unroll
    for (int off = 16; off > 0; off >>= 1) {
        s  += __shfl_down_sync(0xffffffffu, s,  off);
        s2 += __shfl_down_sync(0xffffffffu, s2, off);
    }
    __shared__ float ws[8], ws2[8];
    int wid = tid >> 5, lid = tid & 31;
    if (lid == 0) { ws[wid] = s; ws2[wid] = s2; }
    __syncthreads();
    if (tid == 0) {
        float S = 0.0f, S2 = 0.0f;
        #pragma unroll
        for (int i = 0; i < 8; ++i) { S += ws[i]; S2 += ws2[i]; }
        ws[0] = S; ws2[0] = S2;
    }
    __syncthreads();
    float mean = ws[0] * (1.0f / T0);
    float var  = ws2[0] * (1.0f / T0) - mean * mean;
    float inv  = rsqrtf(var + 1e-5f);
    float a = scale[c] * inv;
    float d = bias[c] - mean * a;
    for (int i = tid; i < T0; i += 256) {
        p[i] = gelu_tanh(fmaf(p[i], a, d));
    }
}

// ---------------------------------------------------------------------------
// Dense conv layer with packed-f32x2 inner loop.
//   block tile = (16*OPC co) x (16*OPT t), 256 threads (16x16).
//   co packed into NP=OPC/2 register pairs; weights pre-packed in SMEM as u64
//   so each bv-pair is one LDS.64. av broadcast-packed with one mov.b64.
// ---------------------------------------------------------------------------
template<int K, int OPC, int OPT>
__global__ __launch_bounds__(256, 2) void conv2_kernel(
    const float* __restrict__ in, const float* __restrict__ w,
    float* __restrict__ out, int Tin, int Tout)
{
    constexpr int COT = 16 * OPC;
    constexpr int TT  = 16 * OPT;
    constexpr int CIT = 8;
    constexpr int IN_W = 2 * TT + K - 1;
    constexpr int NP  = OPC / 2;          // co pairs per thread
    constexpr int WR  = CIT * K;          // reduction cols per chunk

    __shared__ float sIn[CIT][IN_W];
    __shared__ u64  sWp[16 * NP * WR];    // [ty][p][r] packed (co_lo, co_hi)

    const int b   = blockIdx.z;
    const int co0 = blockIdx.y * COT;
    const int t0  = blockIdx.x * TT;
    const int tid = threadIdx.x;
    const int tx  = tid & 15;
    const int ty  = tid >> 4;

    const float* inb = in + (size_t)b * CC * Tin;

    u64 acc2[NP][OPT];
    #pragma unroll
    for (int p = 0; p < NP; ++p)
        #pragma unroll
        for (int i = 0; i < OPT; ++i) acc2[p][i] = 0ull;

    for (int ci0 = 0; ci0 < CC; ci0 += CIT) {
        // stage weights pre-packed: pair p holds (co = ty+16p, co = ty+16(p+NP))
        for (int i = tid; i < COT * WR; i += 256) {
            int col = i / WR;
            int r   = i - col * WR;
            int tyw = col & 15;
            int o   = col >> 4;
            int p    = (o < NP) ? o : o - NP;
            int half = (o < NP) ? 0 : 1;
            ((float*)sWp)[((tyw * NP + p) * WR + r) * 2 + half] =
                w[(size_t)(co0 + col) * (CC * K) + ci0 * K + r];
        }
        // stage input window
        for (int i = tid; i < CIT * IN_W; i += 256) {
            int ci = i / IN_W;
            int pp = i - ci * IN_W;
            int gp = 2 * t0 + pp;
            sIn[ci][pp] = (gp < Tin) ? inb[(size_t)(ci0 + ci) * Tin + gp] : 0.0f;
        }
        __syncthreads();

        #pragma unroll
        for (int ci = 0; ci < CIT; ++ci) {
            #pragma unroll
            for (int j = 0; j < K; ++j) {
                const float* srow = &sIn[ci][2 * tx + j];
                u64 av2[OPT];
                #pragma unroll
                for (int i = 0; i < OPT; ++i)
                    av2[i] = pack2bcast(srow[32 * i]);
                const u64* wrow = &sWp[(ty * NP) * WR + ci * K + j];
                u64 bv2[NP];
                #pragma unroll
                for (int p = 0; p < NP; ++p)
                    bv2[p] = wrow[p * WR];
                #pragma unroll
                for (int p = 0; p < NP; ++p)
                    #pragma unroll
                    for (int i = 0; i < OPT; ++i)
                        fma2(acc2[p][i], bv2[p], av2[i]);
            }
        }
        __syncthreads();
    }

    #pragma unroll
    for (int p = 0; p < NP; ++p) {
        int co_lo = co0 + ty + 16 * p;
        int co_hi = co0 + ty + 16 * (p + NP);
        #pragma unroll
        for (int i = 0; i < OPT; ++i) {
            int t = t0 + tx + 16 * i;
            if (t < Tout) {
                float lo, hi;
                unpack2(acc2[p][i], lo, hi);
                out[((size_t)b * CC + co_lo) * Tout + t] = gelu_tanh(lo);
                out[((size_t)b * CC + co_hi) * Tout + t] = gelu_tanh(hi);
            }
        }
    }
}

// ---------------------------------------------------------------------------
// Tail: time-mean -> proj(512->256)+relu -> gathered 2-layer word head.
// ---------------------------------------------------------------------------
__global__ __launch_bounds__(256) void tail_kernel(
    const float* __restrict__ h, const int* __restrict__ word_ids,
    const float* __restrict__ proj_w, const float* __restrict__ proj_b,
    const float* __restrict__ cls_w1, const float* __restrict__ cls_b1,
    const float* __restrict__ cls_w2, const float* __restrict__ cls_b2,
    float* __restrict__ out)
{
    const int b = blockIdx.x;
    const int tid = threadIdx.x;
    __shared__ float feat[CC];
    __shared__ float pr[256];
    __shared__ float h1[128];

    const float* hb = h + (size_t)b * CC * T6;
    for (int c = tid; c < CC; c += 256) {
        float s = 0.0f;
        const float* row = hb + (size_t)c * T6;
        for (int t = 0; t < T6; ++t) s += row[t];
        feat[c] = s * (1.0f / (float)T6);
    }
    __syncthreads();

    {
        float s = proj_b[tid];
        const float* wr = proj_w + (size_t)tid * CC;
        for (int d = 0; d < CC; ++d) s = fmaf(wr[d], feat[d], s);
        pr[tid] = fmaxf(s, 0.0f);
    }
    __syncthreads();

    const int wid = word_ids[b];
    if (tid < 128) {
        float s = cls_b1[wid * 128 + tid];
        const float* w1 = cls_w1 + (size_t)wid * 256 * 128;
        for (int d = 0; d < 256; ++d)
            s = fmaf(pr[d], w1[d * 128 + tid], s);
        h1[tid] = fmaxf(s, 0.0f);
    }
    __syncthreads();

    if (tid < 5) {
        float s = cls_b2[wid * 5 + tid];
        const float* w2 = cls_w2 + (size_t)wid * 128 * 5;
        for (int d = 0; d < 128; ++d)
            s = fmaf(h1[d], w2[d * 5 + tid], s);
        out[b * 5 + tid] = s;
    }
}

// ---------------------------------------------------------------------------
// Launch
// ---------------------------------------------------------------------------
extern "C" void kernel_launch(void* const* d_in, const int* in_sizes, int n_in,
                              void* d_out, int out_size)
{
    const float* x        = (const float*)d_in[0];
    const int*   word_ids = (const int*)  d_in[1];
    const float* gn_scale = (const float*)d_in[2];
    const float* gn_bias  = (const float*)d_in[3];
    const float* proj_w   = (const float*)d_in[4];
    const float* proj_b   = (const float*)d_in[5];
    const float* cls_w1   = (const float*)d_in[6];
    const float* cls_b1   = (const float*)d_in[7];
    const float* cls_w2   = (const float*)d_in[8];
    const float* cls_b2   = (const float*)d_in[9];
    const float* w0       = (const float*)d_in[10];
    const float* w1       = (const float*)d_in[11];
    const float* w2       = (const float*)d_in[12];
    const float* w3       = (const float*)d_in[13];
    const float* w4       = (const float*)d_in[14];
    const float* w5       = (const float*)d_in[15];
    const float* w6       = (const float*)d_in[16];
    float* out = (float*)d_out;

    float *bufA = nullptr, *bufB = nullptr;
    cudaGetSymbolAddress((void**)&bufA, g_bufA);
    cudaGetSymbolAddress((void**)&bufB, g_bufB);

    conv0_kernel<<<dim3((T0 + C0_TT - 1) / C0_TT, BB), 256>>>(x, w0, bufA);
    gn_gelu_kernel<<<dim3(CC, BB), 256>>>(bufA, gn_scale, gn_bias);

    conv2_kernel<3, 8, 8><<<dim3((T1 + 127) / 128, CC / 128, BB), 256>>>(bufA, w1, bufB, T0, T1);
    conv2_kernel<3, 8, 8><<<dim3((T2 + 127) / 128, CC / 128, BB), 256>>>(bufB, w2, bufA, T1, T2);
    conv2_kernel<3, 8, 8><<<dim3((T3 + 127) / 128, CC / 128, BB), 256>>>(bufA, w3, bufB, T2, T3);
    conv2_kernel<3, 8, 8><<<dim3((T4 + 127) / 128, CC / 128, BB), 256>>>(bufB, w4, bufA, T3, T4);
    conv2_kernel<2, 4, 4><<<dim3((T5 + 63) / 64, CC / 64, BB), 256>>>(bufA, w5, bufB, T4, T5);
    conv2_kernel<2, 4, 2><<<dim3((T6 + 31) / 32, CC / 64, BB), 256>>>(bufB, w6, bufA, T5, T6);

    tail_kernel<<<BB, 256>>>(bufA, word_ids, proj_w, proj_b,
                             cls_w1, cls_b1, cls_w2, cls_b2, out);
}

// round 5
// speedup vs baseline: 2.2768x; 1.9274x over previous
#include <cuda_runtime.h>
#include <cuda_bf16.h>
#include <math.h>
#include <stdint.h>

// ---------------------------------------------------------------------------
// Wav2VecFeats on sm_100 (no tcgen05 in this toolchain target):
// conv1..6 via legacy tensor-core mma.sync m16n8k8 tf32 with exact pre-rounded
// operands. conv0 + groupnorm + tail SIMT.
// Seq lens: 40000 ->7999 ->3999 ->1999 ->999 ->499 ->249 ->124
// R4: fix misaligned STG.64 epilogue (Tout odd => float2 store can be 4B-aligned)
// ---------------------------------------------------------------------------

#define BB 8
#define CC 512
#define L0 40000
#define T0 7999
#define T1 3999
#define T2 1999
#define T3 999
#define T4 499
#define T5 249
#define T6 124

typedef unsigned long long u64;

__device__ float g_bufA[BB * CC * T0];   // ~131 MB
__device__ float g_bufB[BB * CC * T1];   // ~65 MB
__device__ float g_wr[4194304];          // 16 MB rounded+permuted weights

__device__ __forceinline__ float gelu_tanh(float x) {
    const float c0 = 0.7978845608028654f;
    const float c1 = 0.044715f;
    float x3 = x * x * x;
    float t = tanhf(c0 * (x + c1 * x3));
    return 0.5f * x * (1.0f + t);
}

__device__ __forceinline__ float rna_tf32(float v) {
    uint32_t t;
    asm("cvt.rna.tf32.f32 %0, %1;" : "=r"(t) : "f"(v));
    return __uint_as_float(t);
}

__device__ __forceinline__ uint32_t smem_u32(const void* p) {
    uint32_t a;
    asm("{ .reg .u64 t; cvta.to.shared.u64 t, %1; cvt.u32.u64 %0, t; }"
        : "=r"(a) : "l"(p));
    return a;
}

__device__ __forceinline__ void cp_async16(void* dst, const void* src) {
    asm volatile("cp.async.ca.shared.global [%0], [%1], 16;"
                 :: "r"(smem_u32(dst)), "l"(src));
}
__device__ __forceinline__ void cp_async4_guard(void* dst, const void* src, int pred) {
    asm volatile("{\n\t.reg .pred p;\n\tsetp.ne.s32 p, %2, 0;\n\t"
                 "@p cp.async.ca.shared.global [%0], [%1], 4;\n\t"
                 "@!p st.shared.u32 [%0], 0;\n\t}"
                 :: "r"(smem_u32(dst)), "l"(src), "r"(pred));
}
__device__ __forceinline__ void cp_commit() {
    asm volatile("cp.async.commit_group;" ::: "memory");
}
__device__ __forceinline__ void cp_wait1() {
    asm volatile("cp.async.wait_group 1;" ::: "memory");
}
__device__ __forceinline__ void cp_wait0() {
    asm volatile("cp.async.wait_group 0;" ::: "memory");
}

__device__ __forceinline__ void mma_tf32(float* d, const uint32_t* a,
                                         uint32_t b0, uint32_t b1) {
    asm volatile(
        "mma.sync.aligned.m16n8k8.row.col.f32.tf32.tf32.f32 "
        "{%0,%1,%2,%3}, {%4,%5,%6,%7}, {%8,%9}, {%0,%1,%2,%3};"
        : "+f"(d[0]), "+f"(d[1]), "+f"(d[2]), "+f"(d[3])
        : "r"(a[0]), "r"(a[1]), "r"(a[2]), "r"(a[3]), "r"(b0), "r"(b1));
}

// ---------------------------------------------------------------------------
// conv0: (B,40000) -> (B,512,7999), k=10, s=5 (raw output)
// ---------------------------------------------------------------------------
#define C0_TT 128
__global__ __launch_bounds__(256) void conv0_kernel(
    const float* __restrict__ x, const float* __restrict__ w,
    float* __restrict__ out)
{
    __shared__ float sx[5 * C0_TT + 10];
    __shared__ float sw[CC * 10];
    const int b = blockIdx.y;
    const int t0 = blockIdx.x * C0_TT;
    const int tid = threadIdx.x;

    for (int i = tid; i < CC * 10; i += 256) sw[i] = w[i];
    for (int i = tid; i < 5 * C0_TT + 10; i += 256) {
        int gi = 5 * t0 + i;
        sx[i] = (gi < L0) ? x[b * L0 + gi] : 0.0f;
    }
    __syncthreads();

    for (int idx = tid; idx < CC * C0_TT; idx += 256) {
        int tl = idx & (C0_TT - 1);
        int c  = idx >> 7;
        int t  = t0 + tl;
        if (t < T0) {
            float acc = 0.0f;
            const float* wc = &sw[c * 10];
            const float* xp = &sx[5 * tl];
            #pragma unroll
            for (int j = 0; j < 10; ++j) acc = fmaf(wc[j], xp[j], acc);
            out[(b * CC + c) * T0 + t] = acc;
        }
    }
}

// ---------------------------------------------------------------------------
// per-(b,c) norm + affine + gelu + tf32 rounding, in place
// ---------------------------------------------------------------------------
__global__ __launch_bounds__(256) void gn_gelu_kernel(
    float* __restrict__ h, const float* __restrict__ scale,
    const float* __restrict__ bias)
{
    const int c = blockIdx.x;
    const int b = blockIdx.y;
    const int tid = threadIdx.x;
    float* p = h + (size_t)(b * CC + c) * T0;

    float s = 0.0f, s2 = 0.0f;
    for (int i = tid; i < T0; i += 256) {
        float v = p[i];
        s += v; s2 += v * v;
    }
    #pragma unroll
    for (int off = 16; off > 0; off >>= 1) {
        s  += __shfl_down_sync(0xffffffffu, s,  off);
        s2 += __shfl_down_sync(0xffffffffu, s2, off);
    }
    __shared__ float ws[8], ws2[8];
    int wid = tid >> 5, lid = tid & 31;
    if (lid == 0) { ws[wid] = s; ws2[wid] = s2; }
    __syncthreads();
    if (tid == 0) {
        float S = 0.0f, S2 = 0.0f;
        #pragma unroll
        for (int i = 0; i < 8; ++i) { S += ws[i]; S2 += ws2[i]; }
        ws[0] = S; ws2[0] = S2;
    }
    __syncthreads();
    float mean = ws[0] * (1.0f / T0);
    float var  = ws2[0] * (1.0f / T0) - mean * mean;
    float inv  = rsqrtf(var + 1e-5f);
    float a = scale[c] * inv;
    float d = bias[c] - mean * a;
    for (int i = tid; i < T0; i += 256) {
        p[i] = rna_tf32(gelu_tanh(fmaf(p[i], a, d)));
    }
}

// ---------------------------------------------------------------------------
// Weight prep: round to tf32 and permute (co, ci, j) -> plane[j][co][ci]
// ---------------------------------------------------------------------------
__global__ __launch_bounds__(256) void wprep_kernel(
    const float* __restrict__ src, float* __restrict__ dst, int K)
{
    const int co = blockIdx.x;
    for (int i = threadIdx.x; i < 512 * K; i += 256) {
        int ci = i / K;
        int j  = i - ci * K;
        float v = src[(size_t)co * 512 * K + i];
        dst[((size_t)j * 512 + co) * 512 + ci] = rna_tf32(v);
    }
}

// ---------------------------------------------------------------------------
// Tensor-core conv layer: stride 2, kernel K, CTA 128co x 256t, 8 warps,
// warp tile 64x64, m16n8k8 tf32 mma. ci-chunks of 16, cp.async double buffer.
// ---------------------------------------------------------------------------
template<int K, bool ROUND>
__global__ __launch_bounds__(256, 1) void conv_mma_kernel(
    const float* __restrict__ in, const float* __restrict__ wr,
    float* __restrict__ out, int Tin, int Tout)
{
    constexpr int NT   = 256;
    constexpr int KC   = 16;
    constexpr int NCH  = CC / KC;          // 32
    constexpr int SA_W = 20;               // A plane row stride (pad 16->20)
    constexpr int APL  = 128 * SA_W;       // 2560 floats per j-plane
    constexpr int WINW = 2 * NT + K - 1;
    constexpr int WS   = (WINW & 1) ? WINW : WINW + 1;
    constexpr int STGF = K * APL + KC * WS; // floats per stage

    extern __shared__ float smf[];

    const int tid = threadIdx.x;
    const int wrp = tid >> 5;
    const int l   = tid & 31;
    const int q   = l >> 2;                // 0..7
    const int r4  = l & 3;                 // 0..3

    const int b   = blockIdx.z;
    const int co0 = blockIdx.y * 128;
    const int t0  = blockIdx.x * NT;

    const int wm  = wrp & 1;
    const int wn  = wrp >> 1;
    const int cow = wm * 64;
    const int tw  = wn * 64;

    const float* inb = in + (size_t)b * CC * Tin;

    float acc[4][8][4];
    #pragma unroll
    for (int mt = 0; mt < 4; ++mt)
        #pragma unroll
        for (int nt = 0; nt < 8; ++nt)
            #pragma unroll
            for (int e = 0; e < 4; ++e) acc[mt][nt][e] = 0.0f;

    // ---- stage issuance -------------------------------------------------
    auto issue = [&](int c) {
        float* SA = smf + (c & 1) * STGF;
        float* SW = SA + K * APL;
        const int ci0 = c * KC;
        // A: K * 128 rows * 4 x 16B
        for (int i = tid; i < K * 512; i += 256) {
            int j   = i >> 9;
            int rem = i & 511;
            int m   = rem >> 2;
            int seg = rem & 3;
            cp_async16(SA + j * APL + m * SA_W + seg * 4,
                       wr + ((size_t)(j * 512 + co0 + m) * 512 + ci0 + seg * 4));
        }
        // window: KC rows of WINW floats (guarded 4B)
        for (int i = tid; i < KC * WINW; i += 256) {
            int r = i / WINW;
            int p = i - r * WINW;
            int gp = 2 * t0 + p;
            cp_async4_guard(SW + r * WS + p,
                            inb + (size_t)(ci0 + r) * Tin + gp,
                            gp < Tin);
        }
        cp_commit();
    };

    issue(0);

    for (int c = 0; c < NCH; ++c) {
        if (c + 1 < NCH) { issue(c + 1); cp_wait1(); }
        else             { cp_wait0(); }
        __syncthreads();

        const float* SA = smf + (c & 1) * STGF;
        const float* SW = SA + K * APL;

        #pragma unroll 1
        for (int j = 0; j < K; ++j) {
            #pragma unroll
            for (int ks = 0; ks < 2; ++ks) {
                uint32_t afr[4][4];
                #pragma unroll
                for (int mt = 0; mt < 4; ++mt) {
                    const float* ap = SA + j * APL
                                    + (cow + 16 * mt + q) * SA_W + ks * 8 + r4;
                    afr[mt][0] = __float_as_uint(ap[0]);
                    afr[mt][1] = __float_as_uint(ap[8 * SA_W]);
                    afr[mt][2] = __float_as_uint(ap[4]);
                    afr[mt][3] = __float_as_uint(ap[8 * SA_W + 4]);
                }
                #pragma unroll
                for (int nt = 0; nt < 8; ++nt) {
                    const float* bp = SW + (ks * 8 + r4) * WS
                                    + 2 * (tw + 8 * nt + q) + j;
                    uint32_t b0 = __float_as_uint(bp[0]);
                    uint32_t b1 = __float_as_uint(bp[4 * WS]);
                    #pragma unroll
                    for (int mt = 0; mt < 4; ++mt)
                        mma_tf32(acc[mt][nt], afr[mt], b0, b1);
                }
            }
        }
        __syncthreads();
    }

    // ---- epilogue: gelu (+round), scalar stores (Tout odd => no STG.64) --
    float* ob = out + (size_t)b * CC * Tout;
    #pragma unroll
    for (int mt = 0; mt < 4; ++mt) {
        int row0 = co0 + cow + 16 * mt + q;
        #pragma unroll
        for (int nt = 0; nt < 8; ++nt) {
            int t = t0 + tw + 8 * nt + 2 * r4;
            float v0 = gelu_tanh(acc[mt][nt][0]);
            float v1 = gelu_tanh(acc[mt][nt][1]);
            float v2 = gelu_tanh(acc[mt][nt][2]);
            float v3 = gelu_tanh(acc[mt][nt][3]);
            if (ROUND) {
                v0 = rna_tf32(v0); v1 = rna_tf32(v1);
                v2 = rna_tf32(v2); v3 = rna_tf32(v3);
            }
            float* p0 = ob + (size_t)row0 * Tout + t;
            float* p1 = ob + (size_t)(row0 + 8) * Tout + t;
            if (t < Tout)     { p0[0] = v0; p1[0] = v2; }
            if (t + 1 < Tout) { p0[1] = v1; p1[1] = v3; }
        }
    }
}

// ---------------------------------------------------------------------------
// Tail head
// ---------------------------------------------------------------------------
__global__ __launch_bounds__(256) void tail_kernel(
    const float* __restrict__ h, const int* __restrict__ word_ids,
    const float* __restrict__ proj_w, const float* __restrict__ proj_b,
    const float* __restrict__ cls_w1, const float* __restrict__ cls_b1,
    const float* __restrict__ cls_w2, const float* __restrict__ cls_b2,
    float* __restrict__ out)
{
    const int b = blockIdx.x;
    const int tid = threadIdx.x;
    __shared__ float feat[CC];
    __shared__ float pr[256];
    __shared__ float h1[128];

    const float* hb = h + (size_t)b * CC * T6;
    for (int c = tid; c < CC; c += 256) {
        float s = 0.0f;
        const float* row = hb + (size_t)c * T6;
        for (int t = 0; t < T6; ++t) s += row[t];
        feat[c] = s * (1.0f / (float)T6);
    }
    __syncthreads();

    {
        float s = proj_b[tid];
        const float* wrow = proj_w + (size_t)tid * CC;
        for (int d = 0; d < CC; ++d) s = fmaf(wrow[d], feat[d], s);
        pr[tid] = fmaxf(s, 0.0f);
    }
    __syncthreads();

    const int wd = word_ids[b];
    if (tid < 128) {
        float s = cls_b1[wd * 128 + tid];
        const float* w1 = cls_w1 + (size_t)wd * 256 * 128;
        for (int d = 0; d < 256; ++d)
            s = fmaf(pr[d], w1[d * 128 + tid], s);
        h1[tid] = fmaxf(s, 0.0f);
    }
    __syncthreads();

    if (tid < 5) {
        float s = cls_b2[wd * 5 + tid];
        const float* w2 = cls_w2 + (size_t)wd * 128 * 5;
        for (int d = 0; d < 128; ++d)
            s = fmaf(h1[d], w2[d * 5 + tid], s);
        out[b * 5 + tid] = s;
    }
}

// ---------------------------------------------------------------------------
// Launch
// ---------------------------------------------------------------------------
extern "C" void kernel_launch(void* const* d_in, const int* in_sizes, int n_in,
                              void* d_out, int out_size)
{
    const float* x        = (const float*)d_in[0];
    const int*   word_ids = (const int*)  d_in[1];
    const float* gn_scale = (const float*)d_in[2];
    const float* gn_bias  = (const float*)d_in[3];
    const float* proj_w   = (const float*)d_in[4];
    const float* proj_b   = (const float*)d_in[5];
    const float* cls_w1   = (const float*)d_in[6];
    const float* cls_b1   = (const float*)d_in[7];
    const float* cls_w2   = (const float*)d_in[8];
    const float* cls_b2   = (const float*)d_in[9];
    const float* w0       = (const float*)d_in[10];
    const float* w1       = (const float*)d_in[11];
    const float* w2       = (const float*)d_in[12];
    const float* w3       = (const float*)d_in[13];
    const float* w4       = (const float*)d_in[14];
    const float* w5       = (const float*)d_in[15];
    const float* w6       = (const float*)d_in[16];
    float* out = (float*)d_out;

    float *bufA = nullptr, *bufB = nullptr, *wrp = nullptr;
    cudaGetSymbolAddress((void**)&bufA, g_bufA);
    cudaGetSymbolAddress((void**)&bufB, g_bufB);
    cudaGetSymbolAddress((void**)&wrp, g_wr);

    const int PL3 = 3 * 512 * 512;   // floats per K=3 layer block
    const int PL2 = 2 * 512 * 512;
    float* wr1 = wrp;
    float* wr2 = wr1 + PL3;
    float* wr3 = wr2 + PL3;
    float* wr4 = wr3 + PL3;
    float* wr5 = wr4 + PL3;
    float* wr6 = wr5 + PL2;

    // smem sizes (floats per stage * 2 stages * 4B)
    const int STGF3 = 3 * 2560 + 16 * 515;   // 15920
    const int STGF2 = 2 * 2560 + 16 * 513;   // 13328
    const int SM3 = 2 * STGF3 * 4;           // 127360
    const int SM2 = 2 * STGF2 * 4;           // 106624
    cudaFuncSetAttribute(conv_mma_kernel<3, true>,  cudaFuncAttributeMaxDynamicSharedMemorySize, SM3);
    cudaFuncSetAttribute(conv_mma_kernel<2, true>,  cudaFuncAttributeMaxDynamicSharedMemorySize, SM2);
    cudaFuncSetAttribute(conv_mma_kernel<2, false>, cudaFuncAttributeMaxDynamicSharedMemorySize, SM2);

    // weight prep (rounded tf32, permuted to j-planes)
    wprep_kernel<<<512, 256>>>(w1, wr1, 3);
    wprep_kernel<<<512, 256>>>(w2, wr2, 3);
    wprep_kernel<<<512, 256>>>(w3, wr3, 3);
    wprep_kernel<<<512, 256>>>(w4, wr4, 3);
    wprep_kernel<<<512, 256>>>(w5, wr5, 2);
    wprep_kernel<<<512, 256>>>(w6, wr6, 2);

    conv0_kernel<<<dim3((T0 + C0_TT - 1) / C0_TT, BB), 256>>>(x, w0, bufA);
    gn_gelu_kernel<<<dim3(CC, BB), 256>>>(bufA, gn_scale, gn_bias);

    conv_mma_kernel<3, true><<<dim3(16, 4, BB), 256, SM3>>>(bufA, wr1, bufB, T0, T1);
    conv_mma_kernel<3, true><<<dim3( 8, 4, BB), 256, SM3>>>(bufB, wr2, bufA, T1, T2);
    conv_mma_kernel<3, true><<<dim3( 4, 4, BB), 256, SM3>>>(bufA, wr3, bufB, T2, T3);
    conv_mma_kernel<3, true><<<dim3( 2, 4, BB), 256, SM3>>>(bufB, wr4, bufA, T3, T4);
    conv_mma_kernel<2, true><<<dim3( 1, 4, BB), 256, SM2>>>(bufA, wr5, bufB, T4, T5);
    conv_mma_kernel<2, false><<<dim3(1, 4, BB), 256, SM2>>>(bufB, wr6, bufA, T5, T6);

    tail_kernel<<<BB, 256>>>(bufA, word_ids, proj_w, proj_b,
                             cls_w1, cls_b1, cls_w2, cls_b2, out);
}

// round 6
// speedup vs baseline: 3.4573x; 1.5184x over previous
#include <cuda_runtime.h>
#include <cuda_fp16.h>
#include <cuda_bf16.h>
#include <math.h>
#include <stdint.h>

// ---------------------------------------------------------------------------
// Wav2VecFeats on sm_100: conv1..6 via HMMA m16n8k16 fp16 (fp32 accum).
// Intermediates as parity-split half planes [c][t&1][t>>1].
// Seq lens: 40000 ->7999 ->3999 ->1999 ->999 ->499 ->249 ->124
// ---------------------------------------------------------------------------

#define BB 8
#define CC 512
#define L0 40000
#define T0 7999
#define T1 3999
#define T2 1999
#define T3 999
#define T4 499
#define T5 249
#define T6 124

#define HP1 4008
#define HP2 2056

typedef unsigned long long u64;

__device__ float  g_bufA[BB * CC * T0];        // fp32 scratch (conv0 out, conv6 out)
__device__ __half g_H1[(size_t)BB * CC * 2 * HP1]; // ~65.7 MB
__device__ __half g_H2[(size_t)BB * CC * 2 * HP2]; // ~16.8 MB
__device__ __half g_wrh[4194304];              // frag-packed fp16 weights (8 MB)

__device__ __forceinline__ float gelu_tanh(float x) {
    const float c0 = 0.7978845608028654f;
    const float c1 = 0.044715f;
    float x3 = x * x * x;
    float t = tanhf(c0 * (x + c1 * x3));
    return 0.5f * x * (1.0f + t);
}

__device__ __forceinline__ uint32_t smem_u32(const void* p) {
    uint32_t a;
    asm("{ .reg .u64 t; cvta.to.shared.u64 t, %1; cvt.u32.u64 %0, t; }"
        : "=r"(a) : "l"(p));
    return a;
}
__device__ __forceinline__ void cp_async16(void* dst, const void* src) {
    asm volatile("cp.async.ca.shared.global [%0], [%1], 16;"
                 :: "r"(smem_u32(dst)), "l"(src));
}
__device__ __forceinline__ void cp_async4_guard(void* dst, const void* src, int pred) {
    asm volatile("{\n\t.reg .pred p;\n\tsetp.ne.s32 p, %2, 0;\n\t"
                 "@p cp.async.ca.shared.global [%0], [%1], 4;\n\t"
                 "@!p st.shared.u32 [%0], 0;\n\t}"
                 :: "r"(smem_u32(dst)), "l"(src), "r"(pred));
}
__device__ __forceinline__ void cp_commit() {
    asm volatile("cp.async.commit_group;" ::: "memory");
}
__device__ __forceinline__ void cp_wait1() {
    asm volatile("cp.async.wait_group 1;" ::: "memory");
}
__device__ __forceinline__ void cp_wait0() {
    asm volatile("cp.async.wait_group 0;" ::: "memory");
}

__device__ __forceinline__ void mma_f16(float* d, const uint32_t* a,
                                        uint32_t b0, uint32_t b1) {
    asm volatile(
        "mma.sync.aligned.m16n8k16.row.col.f32.f16.f16.f32 "
        "{%0,%1,%2,%3}, {%4,%5,%6,%7}, {%8,%9}, {%0,%1,%2,%3};"
        : "+f"(d[0]), "+f"(d[1]), "+f"(d[2]), "+f"(d[3])
        : "r"(a[0]), "r"(a[1]), "r"(a[2]), "r"(a[3]), "r"(b0), "r"(b1));
}
__device__ __forceinline__ void ldmx2t(uint32_t& b0, uint32_t& b1, uint32_t addr) {
    asm volatile("ldmatrix.sync.aligned.m8n8.x2.trans.shared.b16 {%0,%1}, [%2];"
                 : "=r"(b0), "=r"(b1) : "r"(addr));
}

// ---------------------------------------------------------------------------
// conv0: (B,40000) -> (B,512,7999) fp32, k=10, s=5 (raw)
// ---------------------------------------------------------------------------
#define C0_TT 128
__global__ __launch_bounds__(256) void conv0_kernel(
    const float* __restrict__ x, const float* __restrict__ w,
    float* __restrict__ out)
{
    __shared__ float sx[5 * C0_TT + 10];
    __shared__ float sw[CC * 10];
    const int b = blockIdx.y;
    const int t0 = blockIdx.x * C0_TT;
    const int tid = threadIdx.x;

    for (int i = tid; i < CC * 10; i += 256) sw[i] = w[i];
    for (int i = tid; i < 5 * C0_TT + 10; i += 256) {
        int gi = 5 * t0 + i;
        sx[i] = (gi < L0) ? x[b * L0 + gi] : 0.0f;
    }
    __syncthreads();

    for (int idx = tid; idx < CC * C0_TT; idx += 256) {
        int tl = idx & (C0_TT - 1);
        int c  = idx >> 7;
        int t  = t0 + tl;
        if (t < T0) {
            float acc = 0.0f;
            const float* wc = &sw[c * 10];
            const float* xp = &sx[5 * tl];
            #pragma unroll
            for (int j = 0; j < 10; ++j) acc = fmaf(wc[j], xp[j], acc);
            out[(b * CC + c) * T0 + t] = acc;
        }
    }
}

// ---------------------------------------------------------------------------
// per-(b,c) norm + affine + gelu -> half parity planes in g_H1 (zero-extended)
// ---------------------------------------------------------------------------
__global__ __launch_bounds__(256) void gn_gelu_kernel(
    const float* __restrict__ h, const float* __restrict__ scale,
    const float* __restrict__ bias, __half* __restrict__ outH)
{
    const int c = blockIdx.x;
    const int b = blockIdx.y;
    const int tid = threadIdx.x;
    const float* p = h + (size_t)(b * CC + c) * T0;

    float s = 0.0f, s2 = 0.0f;
    for (int i = tid; i < T0; i += 256) {
        float v = p[i];
        s += v; s2 += v * v;
    }
    #pragma unroll
    for (int off = 16; off > 0; off >>= 1) {
        s  += __shfl_down_sync(0xffffffffu, s,  off);
        s2 += __shfl_down_sync(0xffffffffu, s2, off);
    }
    __shared__ float ws[8], ws2[8];
    int wid = tid >> 5, lid = tid & 31;
    if (lid == 0) { ws[wid] = s; ws2[wid] = s2; }
    __syncthreads();
    if (tid == 0) {
        float S = 0.0f, S2 = 0.0f;
        #pragma unroll
        for (int i = 0; i < 8; ++i) { S += ws[i]; S2 += ws2[i]; }
        ws[0] = S; ws2[0] = S2;
    }
    __syncthreads();
    float mean = ws[0] * (1.0f / T0);
    float var  = ws2[0] * (1.0f / T0) - mean * mean;
    float inv  = rsqrtf(var + 1e-5f);
    float a = scale[c] * inv;
    float d = bias[c] - mean * a;

    __half* ob = outH + ((size_t)(b * CC + c) * 2) * HP1;
    for (int i = tid; i < 8008; i += 256) {
        float v = (i < T0) ? gelu_tanh(fmaf(p[i], a, d)) : 0.0f;
        ob[(size_t)(i & 1) * HP1 + (i >> 1)] = __float2half_rn(v);
    }
}

// ---------------------------------------------------------------------------
// Weight prep (all 6 layers, one launch): fp16 + m16n8k16 A-fragment order.
// dst idx = (((j*32 + kc)*32 + cb)*32 + lane)*8 + h
// ---------------------------------------------------------------------------
__global__ __launch_bounds__(256) void wprep_kernel(
    const float* __restrict__ s1, const float* __restrict__ s2,
    const float* __restrict__ s3, const float* __restrict__ s4,
    const float* __restrict__ s5, const float* __restrict__ s6,
    __half* __restrict__ dstAll)
{
    const int ly = blockIdx.y;
    const float* src = (ly == 0) ? s1 : (ly == 1) ? s2 : (ly == 2) ? s3 :
                       (ly == 3) ? s4 : (ly == 4) ? s5 : s6;
    const int K = (ly < 4) ? 3 : 2;
    size_t base = (ly <= 4) ? (size_t)ly * 786432 : (4u * 786432 + 524288);
    __half* dst = dstAll + base;
    const int total = K * 262144;

    for (int d = blockIdx.x * 256 + threadIdx.x; d < total; d += gridDim.x * 256) {
        int hh   = d & 7;
        int lane = (d >> 3) & 31;
        int cb   = (d >> 8) & 31;
        int kc   = (d >> 13) & 31;
        int j    = d >> 18;
        int q = lane >> 2, r4 = lane & 3;
        int ph = hh >> 1, off = hh & 1;
        int m = q + ((ph & 1) ? 8 : 0);
        int k = 2 * r4 + off + ((ph & 2) ? 8 : 0);
        int co = cb * 16 + m;
        int ci = kc * 16 + k;
        dst[d] = __float2half_rn(src[(size_t)(co * 512 + ci) * K + j]);
    }
}

// ---------------------------------------------------------------------------
// fp16 HMMA conv layer. CTA 128co x NTt, 8 warps (2 x 4), warp 64 x NT/4.
// ci-chunks of 16 (one k16 step), cp.async double buffer.
// Input: half parity planes; Output: half parity planes (zero-extended) or fp32.
// ---------------------------------------------------------------------------
template<int K, int NT, bool F32OUT>
__global__ __launch_bounds__(256, 1) void conv_hmma_kernel(
    const __half* __restrict__ inH, const __half* __restrict__ wh,
    void* __restrict__ outp, int HPin, int HPout, int UW, int Tout)
{
    constexpr int NTT  = NT / 32;              // nt blocks per warp
    constexpr int WU   = NT + 8;               // plane row halves (stride %64==8)
    constexpr int ABY  = K * 4096;             // A bytes per stage
    constexpr int PLB  = 16 * WU * 2;          // plane bytes
    constexpr int STGB = ABY + K * PLB;        // stage bytes
    constexpr int NPAIR = (NT + 2) / 2;        // 4B pairs per plane row

    extern __shared__ char smem[];

    const int tid = threadIdx.x;
    const int wrp = tid >> 5;
    const int l   = tid & 31;
    const int q   = l >> 2;
    const int r4  = l & 3;
    const int wm  = wrp & 1;
    const int wn  = wrp >> 1;
    const int tw  = wn * (NT / 4);

    const int b   = blockIdx.z;
    const int co0 = blockIdx.y * 128;
    const int cb0 = blockIdx.y * 8;
    const int t0  = blockIdx.x * NT;

    float acc[4][NTT][4];
    #pragma unroll
    for (int mt = 0; mt < 4; ++mt)
        #pragma unroll
        for (int nt = 0; nt < NTT; ++nt)
            #pragma unroll
            for (int e = 0; e < 4; ++e) acc[mt][nt][e] = 0.0f;

    auto issue = [&](int c) {
        char* SB = smem + (c & 1) * STGB;
        // A: K * 256 x 16B, contiguous frag-packed halves
        for (int i = tid; i < K * 256; i += 256) {
            int j = i >> 8;
            int x = i & 255;
            cp_async16(SB + j * 4096 + x * 16,
                       wh + ((size_t)((j * 32 + c) * 32 + cb0)) * 256 + x * 8);
        }
        // B: planes 0,1 (parity), guarded 4B pairs
        for (int i = tid; i < 2 * 16 * NPAIR; i += 256) {
            int p  = i / (16 * NPAIR);
            int r  = i - p * (16 * NPAIR);
            int ci = r / NPAIR;
            int v  = 2 * (r - ci * NPAIR);
            int u  = t0 + v;
            cp_async4_guard(SB + ABY + p * PLB + ci * (WU * 2) + v * 2,
                            inH + ((size_t)((b * CC + c * 16 + ci) * 2 + p) * HPin + u),
                            (u + 1 < UW) ? 1 : 0);
        }
        cp_commit();
    };

    issue(0);

    const uint32_t smem_base_u = smem_u32(smem);

    for (int c = 0; c < 32; ++c) {
        if (c + 1 < 32) { issue(c + 1); cp_wait1(); }
        else            { cp_wait0(); }
        __syncthreads();

        char* SB = smem + (c & 1) * STGB;
        const uint32_t su = smem_base_u + (c & 1) * STGB;

        if (K == 3) {
            // plane2[v] = plane0[v+1] (halves), via funnel shift on u32
            const uint32_t* p0 = (const uint32_t*)(SB + ABY);
            uint32_t* p2 = (uint32_t*)(SB + ABY + 2 * PLB);
            constexpr int HW = NT / 2;
            for (int i = tid; i < 16 * HW; i += 256) {
                int ci = i / HW;
                int vi = i - ci * HW;
                const uint32_t* row = p0 + ci * (WU / 2);
                uint32_t lo = row[vi], hi = row[vi + 1];
                p2[ci * (WU / 2) + vi] = __funnelshift_r(lo, hi, 16);
            }
            __syncthreads();
        }

        #pragma unroll
        for (int j = 0; j < K; ++j) {
            uint4 af[4];
            #pragma unroll
            for (int mt = 0; mt < 4; ++mt)
                af[mt] = *(const uint4*)(SB + j * 4096 + (wm * 4 + mt) * 512 + l * 16);
            #pragma unroll
            for (int nt = 0; nt < NTT; ++nt) {
                uint32_t b0, b1;
                uint32_t baddr = su + ABY + j * PLB + (l & 15) * (WU * 2)
                               + (tw + 8 * nt) * 2;
                ldmx2t(b0, b1, baddr);
                #pragma unroll
                for (int mt = 0; mt < 4; ++mt)
                    mma_f16(acc[mt][nt], (const uint32_t*)&af[mt], b0, b1);
            }
        }
        __syncthreads();
    }

    // ---- epilogue -------------------------------------------------------
    if (F32OUT) {
        float* ob = (float*)outp;
        #pragma unroll
        for (int mt = 0; mt < 4; ++mt) {
            int row0 = co0 + wm * 64 + 16 * mt + q;
            #pragma unroll
            for (int nt = 0; nt < NTT; ++nt) {
                int t = t0 + tw + 8 * nt + 2 * r4;
                float v0 = gelu_tanh(acc[mt][nt][0]);
                float v1 = gelu_tanh(acc[mt][nt][1]);
                float v2 = gelu_tanh(acc[mt][nt][2]);
                float v3 = gelu_tanh(acc[mt][nt][3]);
                if (t < Tout) {
                    ob[(size_t)(b * CC + row0) * Tout + t]     = v0;
                    ob[(size_t)(b * CC + row0 + 8) * Tout + t] = v2;
                }
                if (t + 1 < Tout) {
                    ob[(size_t)(b * CC + row0) * Tout + t + 1]     = v1;
                    ob[(size_t)(b * CC + row0 + 8) * Tout + t + 1] = v3;
                }
            }
        }
    } else {
        __half* oh = (__half*)outp;
        #pragma unroll
        for (int mt = 0; mt < 4; ++mt) {
            int row0 = co0 + wm * 64 + 16 * mt + q;
            size_t base0 = (size_t)(b * CC + row0) * 2 * HPout;
            size_t base8 = (size_t)(b * CC + row0 + 8) * 2 * HPout;
            #pragma unroll
            for (int nt = 0; nt < NTT; ++nt) {
                int t = t0 + tw + 8 * nt + 2 * r4;   // even
                int u = t >> 1;
                __half h0 = (t     < Tout) ? __float2half_rn(gelu_tanh(acc[mt][nt][0])) : __half(0.0f);
                __half h1 = (t + 1 < Tout) ? __float2half_rn(gelu_tanh(acc[mt][nt][1])) : __half(0.0f);
                __half h2 = (t     < Tout) ? __float2half_rn(gelu_tanh(acc[mt][nt][2])) : __half(0.0f);
                __half h3 = (t + 1 < Tout) ? __float2half_rn(gelu_tanh(acc[mt][nt][3])) : __half(0.0f);
                oh[base0 + u]        = h0;
                oh[base0 + HPout + u] = h1;
                oh[base8 + u]        = h2;
                oh[base8 + HPout + u] = h3;
            }
        }
    }
}

// ---------------------------------------------------------------------------
// Tail head (reads fp32 conv6 output)
// ---------------------------------------------------------------------------
__global__ __launch_bounds__(256) void tail_kernel(
    const float* __restrict__ h, const int* __restrict__ word_ids,
    const float* __restrict__ proj_w, const float* __restrict__ proj_b,
    const float* __restrict__ cls_w1, const float* __restrict__ cls_b1,
    const float* __restrict__ cls_w2, const float* __restrict__ cls_b2,
    float* __restrict__ out)
{
    const int b = blockIdx.x;
    const int tid = threadIdx.x;
    __shared__ float feat[CC];
    __shared__ float pr[256];
    __shared__ float h1[128];

    const float* hb = h + (size_t)b * CC * T6;
    for (int c = tid; c < CC; c += 256) {
        float s = 0.0f;
        const float* row = hb + (size_t)c * T6;
        for (int t = 0; t < T6; ++t) s += row[t];
        feat[c] = s * (1.0f / (float)T6);
    }
    __syncthreads();

    {
        float s = proj_b[tid];
        const float* wrow = proj_w + (size_t)tid * CC;
        for (int d = 0; d < CC; ++d) s = fmaf(wrow[d], feat[d], s);
        pr[tid] = fmaxf(s, 0.0f);
    }
    __syncthreads();

    const int wd = word_ids[b];
    if (tid < 128) {
        float s = cls_b1[wd * 128 + tid];
        const float* w1 = cls_w1 + (size_t)wd * 256 * 128;
        for (int d = 0; d < 256; ++d)
            s = fmaf(pr[d], w1[d * 128 + tid], s);
        h1[tid] = fmaxf(s, 0.0f);
    }
    __syncthreads();

    if (tid < 5) {
        float s = cls_b2[wd * 5 + tid];
        const float* w2 = cls_w2 + (size_t)wd * 128 * 5;
        for (int d = 0; d < 128; ++d)
            s = fmaf(h1[d], w2[d * 5 + tid], s);
        out[b * 5 + tid] = s;
    }
}

// ---------------------------------------------------------------------------
// Launch
// ---------------------------------------------------------------------------
extern "C" void kernel_launch(void* const* d_in, const int* in_sizes, int n_in,
                              void* d_out, int out_size)
{
    const float* x        = (const float*)d_in[0];
    const int*   word_ids = (const int*)  d_in[1];
    const float* gn_scale = (const float*)d_in[2];
    const float* gn_bias  = (const float*)d_in[3];
    const float* proj_w   = (const float*)d_in[4];
    const float* proj_b   = (const float*)d_in[5];
    const float* cls_w1   = (const float*)d_in[6];
    const float* cls_b1   = (const float*)d_in[7];
    const float* cls_w2   = (const float*)d_in[8];
    const float* cls_b2   = (const float*)d_in[9];
    const float* w0       = (const float*)d_in[10];
    const float* w1       = (const float*)d_in[11];
    const float* w2       = (const float*)d_in[12];
    const float* w3       = (const float*)d_in[13];
    const float* w4       = (const float*)d_in[14];
    const float* w5       = (const float*)d_in[15];
    const float* w6       = (const float*)d_in[16];
    float* out = (float*)d_out;

    float *bufA = nullptr;
    __half *H1 = nullptr, *H2 = nullptr, *wrh = nullptr;
    cudaGetSymbolAddress((void**)&bufA, g_bufA);
    cudaGetSymbolAddress((void**)&H1, g_H1);
    cudaGetSymbolAddress((void**)&H2, g_H2);
    cudaGetSymbolAddress((void**)&wrh, g_wrh);

    const size_t PL3 = 786432;   // halves per K=3 layer
    __half* wr1 = wrh;
    __half* wr2 = wr1 + PL3;
    __half* wr3 = wr2 + PL3;
    __half* wr4 = wr3 + PL3;
    __half* wr5 = wr4 + PL3;
    __half* wr6 = wr5 + 524288;

    // smem per variant: 2 * (K*4096 + K*16*(NT+8)*2)
    const int SM3_256 = 2 * (3 * 4096 + 3 * 16 * 264 * 2);   // 75264
    const int SM3_128 = 2 * (3 * 4096 + 3 * 16 * 136 * 2);   // 50688
    const int SM2_128 = 2 * (2 * 4096 + 2 * 16 * 136 * 2);   // 33792
    cudaFuncSetAttribute((const void*)conv_hmma_kernel<3, 256, false>,
                         cudaFuncAttributeMaxDynamicSharedMemorySize, SM3_256);
    cudaFuncSetAttribute((const void*)conv_hmma_kernel<3, 128, false>,
                         cudaFuncAttributeMaxDynamicSharedMemorySize, SM3_128);
    cudaFuncSetAttribute((const void*)conv_hmma_kernel<2, 128, false>,
                         cudaFuncAttributeMaxDynamicSharedMemorySize, SM2_128);
    cudaFuncSetAttribute((const void*)conv_hmma_kernel<2, 128, true>,
                         cudaFuncAttributeMaxDynamicSharedMemorySize, SM2_128);

    wprep_kernel<<<dim3(96, 6), 256>>>(w1, w2, w3, w4, w5, w6, wrh);
    conv0_kernel<<<dim3((T0 + C0_TT - 1) / C0_TT, BB), 256>>>(x, w0, bufA);
    gn_gelu_kernel<<<dim3(CC, BB), 256>>>(bufA, gn_scale, gn_bias, H1);

    conv_hmma_kernel<3, 256, false><<<dim3(16, 4, BB), 256, SM3_256>>>(
        H1, wr1, H2, HP1, HP2, 4004, T1);
    conv_hmma_kernel<3, 256, false><<<dim3(8, 4, BB), 256, SM3_256>>>(
        H2, wr2, H1, HP2, HP1, 2048, T2);
    conv_hmma_kernel<3, 256, false><<<dim3(4, 4, BB), 256, SM3_256>>>(
        H1, wr3, H2, HP1, HP2, 1024, T3);
    conv_hmma_kernel<3, 128, false><<<dim3(4, 4, BB), 256, SM3_128>>>(
        H2, wr4, H1, HP2, HP1, 512, T4);
    conv_hmma_kernel<2, 128, false><<<dim3(2, 4, BB), 256, SM2_128>>>(
        H1, wr5, H2, HP1, HP2, 256, T5);
    conv_hmma_kernel<2, 128, true><<<dim3(1, 4, BB), 256, SM2_128>>>(
        H2, wr6, bufA, HP2, 0, 128, T6);

    tail_kernel<<<BB, 256>>>(bufA, word_ids, proj_w, proj_b,
                             cls_w1, cls_b1, cls_w2, cls_b2, out);
}

// round 7
// speedup vs baseline: 3.4574x; 1.0000x over previous
#include <cuda_runtime.h>
#include <cuda_fp16.h>
#include <cuda_bf16.h>
#include <math.h>
#include <stdint.h>

// ---------------------------------------------------------------------------
// Wav2VecFeats on sm_100: conv1..6 via HMMA m16n8k16 fp16 (fp32 accum).
// Intermediates as parity-split half planes [c][t&1][t>>1].
// Seq lens: 40000 ->7999 ->3999 ->1999 ->999 ->499 ->249 ->124
// ---------------------------------------------------------------------------

#define BB 8
#define CC 512
#define L0 40000
#define T0 7999
#define T1 3999
#define T2 1999
#define T3 999
#define T4 499
#define T5 249
#define T6 124

#define HP1 4008
#define HP2 2056

typedef unsigned long long u64;

__device__ float  g_bufA[BB * CC * T0];        // fp32 scratch (conv0 out, conv6 out)
__device__ __half g_H1[(size_t)BB * CC * 2 * HP1]; // ~65.7 MB
__device__ __half g_H2[(size_t)BB * CC * 2 * HP2]; // ~16.8 MB
__device__ __half g_wrh[4194304];              // frag-packed fp16 weights (8 MB)

__device__ __forceinline__ float gelu_tanh(float x) {
    const float c0 = 0.7978845608028654f;
    const float c1 = 0.044715f;
    float x3 = x * x * x;
    float t = tanhf(c0 * (x + c1 * x3));
    return 0.5f * x * (1.0f + t);
}

__device__ __forceinline__ uint32_t smem_u32(const void* p) {
    uint32_t a;
    asm("{ .reg .u64 t; cvta.to.shared.u64 t, %1; cvt.u32.u64 %0, t; }"
        : "=r"(a) : "l"(p));
    return a;
}
__device__ __forceinline__ void cp_async16(void* dst, const void* src) {
    asm volatile("cp.async.ca.shared.global [%0], [%1], 16;"
                 :: "r"(smem_u32(dst)), "l"(src));
}
__device__ __forceinline__ void cp_async4_guard(void* dst, const void* src, int pred) {
    asm volatile("{\n\t.reg .pred p;\n\tsetp.ne.s32 p, %2, 0;\n\t"
                 "@p cp.async.ca.shared.global [%0], [%1], 4;\n\t"
                 "@!p st.shared.u32 [%0], 0;\n\t}"
                 :: "r"(smem_u32(dst)), "l"(src), "r"(pred));
}
__device__ __forceinline__ void cp_commit() {
    asm volatile("cp.async.commit_group;" ::: "memory");
}
__device__ __forceinline__ void cp_wait1() {
    asm volatile("cp.async.wait_group 1;" ::: "memory");
}
__device__ __forceinline__ void cp_wait0() {
    asm volatile("cp.async.wait_group 0;" ::: "memory");
}

__device__ __forceinline__ void mma_f16(float* d, const uint32_t* a,
                                        uint32_t b0, uint32_t b1) {
    asm volatile(
        "mma.sync.aligned.m16n8k16.row.col.f32.f16.f16.f32 "
        "{%0,%1,%2,%3}, {%4,%5,%6,%7}, {%8,%9}, {%0,%1,%2,%3};"
        : "+f"(d[0]), "+f"(d[1]), "+f"(d[2]), "+f"(d[3])
        : "r"(a[0]), "r"(a[1]), "r"(a[2]), "r"(a[3]), "r"(b0), "r"(b1));
}
__device__ __forceinline__ void ldmx2t(uint32_t& b0, uint32_t& b1, uint32_t addr) {
    asm volatile("ldmatrix.sync.aligned.m8n8.x2.trans.shared.b16 {%0,%1}, [%2];"
                 : "=r"(b0), "=r"(b1) : "r"(addr));
}

// ---------------------------------------------------------------------------
// conv0: (B,40000) -> (B,512,7999) fp32, k=10, s=5 (raw)
// ---------------------------------------------------------------------------
#define C0_TT 128
__global__ __launch_bounds__(256) void conv0_kernel(
    const float* __restrict__ x, const float* __restrict__ w,
    float* __restrict__ out)
{
    __shared__ float sx[5 * C0_TT + 10];
    __shared__ float sw[CC * 10];
    const int b = blockIdx.y;
    const int t0 = blockIdx.x * C0_TT;
    const int tid = threadIdx.x;

    for (int i = tid; i < CC * 10; i += 256) sw[i] = w[i];
    for (int i = tid; i < 5 * C0_TT + 10; i += 256) {
        int gi = 5 * t0 + i;
        sx[i] = (gi < L0) ? x[b * L0 + gi] : 0.0f;
    }
    __syncthreads();

    for (int idx = tid; idx < CC * C0_TT; idx += 256) {
        int tl = idx & (C0_TT - 1);
        int c  = idx >> 7;
        int t  = t0 + tl;
        if (t < T0) {
            float acc = 0.0f;
            const float* wc = &sw[c * 10];
            const float* xp = &sx[5 * tl];
            #pragma unroll
            for (int j = 0; j < 10; ++j) acc = fmaf(wc[j], xp[j], acc);
            out[(b * CC + c) * T0 + t] = acc;
        }
    }
}

// ---------------------------------------------------------------------------
// per-(b,c) norm + affine + gelu -> half parity planes in g_H1 (zero-extended)
// ---------------------------------------------------------------------------
__global__ __launch_bounds__(256) void gn_gelu_kernel(
    const float* __restrict__ h, const float* __restrict__ scale,
    const float* __restrict__ bias, __half* __restrict__ outH)
{
    const int c = blockIdx.x;
    const int b = blockIdx.y;
    const int tid = threadIdx.x;
    const float* p = h + (size_t)(b * CC + c) * T0;

    float s = 0.0f, s2 = 0.0f;
    for (int i = tid; i < T0; i += 256) {
        float v = p[i];
        s += v; s2 += v * v;
    }
    #pragma unroll
    for (int off = 16; off > 0; off >>= 1) {
        s  += __shfl_down_sync(0xffffffffu, s,  off);
        s2 += __shfl_down_sync(0xffffffffu, s2, off);
    }
    __shared__ float ws[8], ws2[8];
    int wid = tid >> 5, lid = tid & 31;
    if (lid == 0) { ws[wid] = s; ws2[wid] = s2; }
    __syncthreads();
    if (tid == 0) {
        float S = 0.0f, S2 = 0.0f;
        #pragma unroll
        for (int i = 0; i < 8; ++i) { S += ws[i]; S2 += ws2[i]; }
        ws[0] = S; ws2[0] = S2;
    }
    __syncthreads();
    float mean = ws[0] * (1.0f / T0);
    float var  = ws2[0] * (1.0f / T0) - mean * mean;
    float inv  = rsqrtf(var + 1e-5f);
    float a = scale[c] * inv;
    float d = bias[c] - mean * a;

    __half* ob = outH + ((size_t)(b * CC + c) * 2) * HP1;
    for (int i = tid; i < 8008; i += 256) {
        float v = (i < T0) ? gelu_tanh(fmaf(p[i], a, d)) : 0.0f;
        ob[(size_t)(i & 1) * HP1 + (i >> 1)] = __float2half_rn(v);
    }
}

// ---------------------------------------------------------------------------
// Weight prep (all 6 layers, one launch): fp16 + m16n8k16 A-fragment order.
// dst idx = (((j*32 + kc)*32 + cb)*32 + lane)*8 + h
// ---------------------------------------------------------------------------
__global__ __launch_bounds__(256) void wprep_kernel(
    const float* __restrict__ s1, const float* __restrict__ s2,
    const float* __restrict__ s3, const float* __restrict__ s4,
    const float* __restrict__ s5, const float* __restrict__ s6,
    __half* __restrict__ dstAll)
{
    const int ly = blockIdx.y;
    const float* src = (ly == 0) ? s1 : (ly == 1) ? s2 : (ly == 2) ? s3 :
                       (ly == 3) ? s4 : (ly == 4) ? s5 : s6;
    const int K = (ly < 4) ? 3 : 2;
    size_t base = (ly <= 4) ? (size_t)ly * 786432 : (4u * 786432 + 524288);
    __half* dst = dstAll + base;
    const int total = K * 262144;

    for (int d = blockIdx.x * 256 + threadIdx.x; d < total; d += gridDim.x * 256) {
        int hh   = d & 7;
        int lane = (d >> 3) & 31;
        int cb   = (d >> 8) & 31;
        int kc   = (d >> 13) & 31;
        int j    = d >> 18;
        int q = lane >> 2, r4 = lane & 3;
        int ph = hh >> 1, off = hh & 1;
        int m = q + ((ph & 1) ? 8 : 0);
        int k = 2 * r4 + off + ((ph & 2) ? 8 : 0);
        int co = cb * 16 + m;
        int ci = kc * 16 + k;
        dst[d] = __float2half_rn(src[(size_t)(co * 512 + ci) * K + j]);
    }
}

// ---------------------------------------------------------------------------
// fp16 HMMA conv layer. CTA 128co x NTt, 8 warps (2 x 4), warp 64 x NT/4.
// ci-chunks of 16 (one k16 step), cp.async double buffer.
// Input: half parity planes; Output: half parity planes (zero-extended) or fp32.
// ---------------------------------------------------------------------------
template<int K, int NT, bool F32OUT>
__global__ __launch_bounds__(256, 1) void conv_hmma_kernel(
    const __half* __restrict__ inH, const __half* __restrict__ wh,
    void* __restrict__ outp, int HPin, int HPout, int UW, int Tout)
{
    constexpr int NTT  = NT / 32;              // nt blocks per warp
    constexpr int WU   = NT + 8;               // plane row halves (stride %64==8)
    constexpr int ABY  = K * 4096;             // A bytes per stage
    constexpr int PLB  = 16 * WU * 2;          // plane bytes
    constexpr int STGB = ABY + K * PLB;        // stage bytes
    constexpr int NPAIR = (NT + 2) / 2;        // 4B pairs per plane row

    extern __shared__ char smem[];

    const int tid = threadIdx.x;
    const int wrp = tid >> 5;
    const int l   = tid & 31;
    const int q   = l >> 2;
    const int r4  = l & 3;
    const int wm  = wrp & 1;
    const int wn  = wrp >> 1;
    const int tw  = wn * (NT / 4);

    const int b   = blockIdx.z;
    const int co0 = blockIdx.y * 128;
    const int cb0 = blockIdx.y * 8;
    const int t0  = blockIdx.x * NT;

    float acc[4][NTT][4];
    #pragma unroll
    for (int mt = 0; mt < 4; ++mt)
        #pragma unroll
        for (int nt = 0; nt < NTT; ++nt)
            #pragma unroll
            for (int e = 0; e < 4; ++e) acc[mt][nt][e] = 0.0f;

    auto issue = [&](int c) {
        char* SB = smem + (c & 1) * STGB;
        // A: K * 256 x 16B, contiguous frag-packed halves
        for (int i = tid; i < K * 256; i += 256) {
            int j = i >> 8;
            int x = i & 255;
            cp_async16(SB + j * 4096 + x * 16,
                       wh + ((size_t)((j * 32 + c) * 32 + cb0)) * 256 + x * 8);
        }
        // B: planes 0,1 (parity), guarded 4B pairs
        for (int i = tid; i < 2 * 16 * NPAIR; i += 256) {
            int p  = i / (16 * NPAIR);
            int r  = i - p * (16 * NPAIR);
            int ci = r / NPAIR;
            int v  = 2 * (r - ci * NPAIR);
            int u  = t0 + v;
            cp_async4_guard(SB + ABY + p * PLB + ci * (WU * 2) + v * 2,
                            inH + ((size_t)((b * CC + c * 16 + ci) * 2 + p) * HPin + u),
                            (u + 1 < UW) ? 1 : 0);
        }
        cp_commit();
    };

    issue(0);

    const uint32_t smem_base_u = smem_u32(smem);

    for (int c = 0; c < 32; ++c) {
        if (c + 1 < 32) { issue(c + 1); cp_wait1(); }
        else            { cp_wait0(); }
        __syncthreads();

        char* SB = smem + (c & 1) * STGB;
        const uint32_t su = smem_base_u + (c & 1) * STGB;

        if (K == 3) {
            // plane2[v] = plane0[v+1] (halves), via funnel shift on u32
            const uint32_t* p0 = (const uint32_t*)(SB + ABY);
            uint32_t* p2 = (uint32_t*)(SB + ABY + 2 * PLB);
            constexpr int HW = NT / 2;
            for (int i = tid; i < 16 * HW; i += 256) {
                int ci = i / HW;
                int vi = i - ci * HW;
                const uint32_t* row = p0 + ci * (WU / 2);
                uint32_t lo = row[vi], hi = row[vi + 1];
                p2[ci * (WU / 2) + vi] = __funnelshift_r(lo, hi, 16);
            }
            __syncthreads();
        }

        #pragma unroll
        for (int j = 0; j < K; ++j) {
            uint4 af[4];
            #pragma unroll
            for (int mt = 0; mt < 4; ++mt)
                af[mt] = *(const uint4*)(SB + j * 4096 + (wm * 4 + mt) * 512 + l * 16);
            #pragma unroll
            for (int nt = 0; nt < NTT; ++nt) {
                uint32_t b0, b1;
                uint32_t baddr = su + ABY + j * PLB + (l & 15) * (WU * 2)
                               + (tw + 8 * nt) * 2;
                ldmx2t(b0, b1, baddr);
                #pragma unroll
                for (int mt = 0; mt < 4; ++mt)
                    mma_f16(acc[mt][nt], (const uint32_t*)&af[mt], b0, b1);
            }
        }
        __syncthreads();
    }

    // ---- epilogue -------------------------------------------------------
    if (F32OUT) {
        float* ob = (float*)outp;
        #pragma unroll
        for (int mt = 0; mt < 4; ++mt) {
            int row0 = co0 + wm * 64 + 16 * mt + q;
            #pragma unroll
            for (int nt = 0; nt < NTT; ++nt) {
                int t = t0 + tw + 8 * nt + 2 * r4;
                float v0 = gelu_tanh(acc[mt][nt][0]);
                float v1 = gelu_tanh(acc[mt][nt][1]);
                float v2 = gelu_tanh(acc[mt][nt][2]);
                float v3 = gelu_tanh(acc[mt][nt][3]);
                if (t < Tout) {
                    ob[(size_t)(b * CC + row0) * Tout + t]     = v0;
                    ob[(size_t)(b * CC + row0 + 8) * Tout + t] = v2;
                }
                if (t + 1 < Tout) {
                    ob[(size_t)(b * CC + row0) * Tout + t + 1]     = v1;
                    ob[(size_t)(b * CC + row0 + 8) * Tout + t + 1] = v3;
                }
            }
        }
    } else {
        __half* oh = (__half*)outp;
        #pragma unroll
        for (int mt = 0; mt < 4; ++mt) {
            int row0 = co0 + wm * 64 + 16 * mt + q;
            size_t base0 = (size_t)(b * CC + row0) * 2 * HPout;
            size_t base8 = (size_t)(b * CC + row0 + 8) * 2 * HPout;
            #pragma unroll
            for (int nt = 0; nt < NTT; ++nt) {
                int t = t0 + tw + 8 * nt + 2 * r4;   // even
                int u = t >> 1;
                __half h0 = (t     < Tout) ? __float2half_rn(gelu_tanh(acc[mt][nt][0])) : __half(0.0f);
                __half h1 = (t + 1 < Tout) ? __float2half_rn(gelu_tanh(acc[mt][nt][1])) : __half(0.0f);
                __half h2 = (t     < Tout) ? __float2half_rn(gelu_tanh(acc[mt][nt][2])) : __half(0.0f);
                __half h3 = (t + 1 < Tout) ? __float2half_rn(gelu_tanh(acc[mt][nt][3])) : __half(0.0f);
                oh[base0 + u]        = h0;
                oh[base0 + HPout + u] = h1;
                oh[base8 + u]        = h2;
                oh[base8 + HPout + u] = h3;
            }
        }
    }
}

// ---------------------------------------------------------------------------
// Tail head (reads fp32 conv6 output)
// ---------------------------------------------------------------------------
__global__ __launch_bounds__(256) void tail_kernel(
    const float* __restrict__ h, const int* __restrict__ word_ids,
    const float* __restrict__ proj_w, const float* __restrict__ proj_b,
    const float* __restrict__ cls_w1, const float* __restrict__ cls_b1,
    const float* __restrict__ cls_w2, const float* __restrict__ cls_b2,
    float* __restrict__ out)
{
    const int b = blockIdx.x;
    const int tid = threadIdx.x;
    __shared__ float feat[CC];
    __shared__ float pr[256];
    __shared__ float h1[128];

    const float* hb = h + (size_t)b * CC * T6;
    for (int c = tid; c < CC; c += 256) {
        float s = 0.0f;
        const float* row = hb + (size_t)c * T6;
        for (int t = 0; t < T6; ++t) s += row[t];
        feat[c] = s * (1.0f / (float)T6);
    }
    __syncthreads();

    {
        float s = proj_b[tid];
        const float* wrow = proj_w + (size_t)tid * CC;
        for (int d = 0; d < CC; ++d) s = fmaf(wrow[d], feat[d], s);
        pr[tid] = fmaxf(s, 0.0f);
    }
    __syncthreads();

    const int wd = word_ids[b];
    if (tid < 128) {
        float s = cls_b1[wd * 128 + tid];
        const float* w1 = cls_w1 + (size_t)wd * 256 * 128;
        for (int d = 0; d < 256; ++d)
            s = fmaf(pr[d], w1[d * 128 + tid], s);
        h1[tid] = fmaxf(s, 0.0f);
    }
    __syncthreads();

    if (tid < 5) {
        float s = cls_b2[wd * 5 + tid];
        const float* w2 = cls_w2 + (size_t)wd * 128 * 5;
        for (int d = 0; d < 128; ++d)
            s = fmaf(h1[d], w2[d * 5 + tid], s);
        out[b * 5 + tid] = s;
    }
}

// ---------------------------------------------------------------------------
// Launch
// ---------------------------------------------------------------------------
extern "C" void kernel_launch(void* const* d_in, const int* in_sizes, int n_in,
                              void* d_out, int out_size)
{
    const float* x        = (const float*)d_in[0];
    const int*   word_ids = (const int*)  d_in[1];
    const float* gn_scale = (const float*)d_in[2];
    const float* gn_bias  = (const float*)d_in[3];
    const float* proj_w   = (const float*)d_in[4];
    const float* proj_b   = (const float*)d_in[5];
    const float* cls_w1   = (const float*)d_in[6];
    const float* cls_b1   = (const float*)d_in[7];
    const float* cls_w2   = (const float*)d_in[8];
    const float* cls_b2   = (const float*)d_in[9];
    const float* w0       = (const float*)d_in[10];
    const float* w1       = (const float*)d_in[11];
    const float* w2       = (const float*)d_in[12];
    const float* w3       = (const float*)d_in[13];
    const float* w4       = (const float*)d_in[14];
    const float* w5       = (const float*)d_in[15];
    const float* w6       = (const float*)d_in[16];
    float* out = (float*)d_out;

    float *bufA = nullptr;
    __half *H1 = nullptr, *H2 = nullptr, *wrh = nullptr;
    cudaGetSymbolAddress((void**)&bufA, g_bufA);
    cudaGetSymbolAddress((void**)&H1, g_H1);
    cudaGetSymbolAddress((void**)&H2, g_H2);
    cudaGetSymbolAddress((void**)&wrh, g_wrh);

    const size_t PL3 = 786432;   // halves per K=3 layer
    __half* wr1 = wrh;
    __half* wr2 = wr1 + PL3;
    __half* wr3 = wr2 + PL3;
    __half* wr4 = wr3 + PL3;
    __half* wr5 = wr4 + PL3;
    __half* wr6 = wr5 + 524288;

    // smem per variant: 2 * (K*4096 + K*16*(NT+8)*2)
    const int SM3_256 = 2 * (3 * 4096 + 3 * 16 * 264 * 2);   // 75264
    const int SM3_128 = 2 * (3 * 4096 + 3 * 16 * 136 * 2);   // 50688
    const int SM2_128 = 2 * (2 * 4096 + 2 * 16 * 136 * 2);   // 33792
    cudaFuncSetAttribute((const void*)conv_hmma_kernel<3, 256, false>,
                         cudaFuncAttributeMaxDynamicSharedMemorySize, SM3_256);
    cudaFuncSetAttribute((const void*)conv_hmma_kernel<3, 128, false>,
                         cudaFuncAttributeMaxDynamicSharedMemorySize, SM3_128);
    cudaFuncSetAttribute((const void*)conv_hmma_kernel<2, 128, false>,
                         cudaFuncAttributeMaxDynamicSharedMemorySize, SM2_128);
    cudaFuncSetAttribute((const void*)conv_hmma_kernel<2, 128, true>,
                         cudaFuncAttributeMaxDynamicSharedMemorySize, SM2_128);

    wprep_kernel<<<dim3(96, 6), 256>>>(w1, w2, w3, w4, w5, w6, wrh);
    conv0_kernel<<<dim3((T0 + C0_TT - 1) / C0_TT, BB), 256>>>(x, w0, bufA);
    gn_gelu_kernel<<<dim3(CC, BB), 256>>>(bufA, gn_scale, gn_bias, H1);

    conv_hmma_kernel<3, 256, false><<<dim3(16, 4, BB), 256, SM3_256>>>(
        H1, wr1, H2, HP1, HP2, 4004, T1);
    conv_hmma_kernel<3, 256, false><<<dim3(8, 4, BB), 256, SM3_256>>>(
        H2, wr2, H1, HP2, HP1, 2048, T2);
    conv_hmma_kernel<3, 256, false><<<dim3(4, 4, BB), 256, SM3_256>>>(
        H1, wr3, H2, HP1, HP2, 1024, T3);
    conv_hmma_kernel<3, 128, false><<<dim3(4, 4, BB), 256, SM3_128>>>(
        H2, wr4, H1, HP2, HP1, 512, T4);
    conv_hmma_kernel<2, 128, false><<<dim3(2, 4, BB), 256, SM2_128>>>(
        H1, wr5, H2, HP1, HP2, 256, T5);
    conv_hmma_kernel<2, 128, true><<<dim3(1, 4, BB), 256, SM2_128>>>(
        H2, wr6, bufA, HP2, 0, 128, T6);

    tail_kernel<<<BB, 256>>>(bufA, word_ids, proj_w, proj_b,
                             cls_w1, cls_b1, cls_w2, cls_b2, out);
}

// round 8
// speedup vs baseline: 5.1519x; 1.4901x over previous
#include <cuda_runtime.h>
#include <cuda_fp16.h>
#include <cuda_bf16.h>
#include <math.h>
#include <stdint.h>

// ---------------------------------------------------------------------------
// Wav2VecFeats on sm_100: conv1..6 via HMMA m16n8k16 fp16 (fp32 accum).
// Intermediates as parity-split half planes [c][t&1][t>>1].
// R7: power-of-2 16B staging, precomputed slot pointers, 3-stage pipeline.
// ---------------------------------------------------------------------------

#define BB 8
#define CC 512
#define L0 40000
#define T0 7999
#define T1 3999
#define T2 1999
#define T3 999
#define T4 499
#define T5 249
#define T6 124

#define HP1 4008
#define HP2 2056

typedef unsigned long long u64;

__device__ float  g_bufA[BB * CC * T0];                     // fp32 scratch
__device__ __half g_H1[(size_t)BB * CC * 2 * HP1 + 8192];   // padded
__device__ __half g_H2[(size_t)BB * CC * 2 * HP2 + 8192];   // padded
__device__ __half g_wrh[4194304];                           // frag-packed weights

__device__ __forceinline__ float gelu_tanh(float x) {
    const float c0 = 0.7978845608028654f;
    const float c1 = 0.044715f;
    float x3 = x * x * x;
    float t = tanhf(c0 * (x + c1 * x3));
    return 0.5f * x * (1.0f + t);
}

__device__ __forceinline__ uint32_t smem_u32(const void* p) {
    uint32_t a;
    asm("{ .reg .u64 t; cvta.to.shared.u64 t, %1; cvt.u32.u64 %0, t; }"
        : "=r"(a) : "l"(p));
    return a;
}
__device__ __forceinline__ void cp_async16(void* dst, const void* src) {
    asm volatile("cp.async.ca.shared.global [%0], [%1], 16;"
                 :: "r"(smem_u32(dst)), "l"(src));
}
__device__ __forceinline__ void cp_async4(void* dst, const void* src) {
    asm volatile("cp.async.ca.shared.global [%0], [%1], 4;"
                 :: "r"(smem_u32(dst)), "l"(src));
}
__device__ __forceinline__ void cp_commit() {
    asm volatile("cp.async.commit_group;" ::: "memory");
}
template<int N> __device__ __forceinline__ void cp_wait() {
    asm volatile("cp.async.wait_group %0;" :: "n"(N) : "memory");
}

__device__ __forceinline__ void mma_f16(float* d, const uint32_t* a,
                                        uint32_t b0, uint32_t b1) {
    asm volatile(
        "mma.sync.aligned.m16n8k16.row.col.f32.f16.f16.f32 "
        "{%0,%1,%2,%3}, {%4,%5,%6,%7}, {%8,%9}, {%0,%1,%2,%3};"
        : "+f"(d[0]), "+f"(d[1]), "+f"(d[2]), "+f"(d[3])
        : "r"(a[0]), "r"(a[1]), "r"(a[2]), "r"(a[3]), "r"(b0), "r"(b1));
}
__device__ __forceinline__ void ldmx2t(uint32_t& b0, uint32_t& b1, uint32_t addr) {
    asm volatile("ldmatrix.sync.aligned.m8n8.x2.trans.shared.b16 {%0,%1}, [%2];"
                 : "=r"(b0), "=r"(b1) : "r"(addr));
}

// ---------------------------------------------------------------------------
// conv0: (B,40000) -> (B,512,7999) fp32, k=10, s=5 (raw)
// ---------------------------------------------------------------------------
#define C0_TT 128
__global__ __launch_bounds__(256) void conv0_kernel(
    const float* __restrict__ x, const float* __restrict__ w,
    float* __restrict__ out)
{
    __shared__ float sx[5 * C0_TT + 10];
    __shared__ float sw[CC * 10];
    const int b = blockIdx.y;
    const int t0 = blockIdx.x * C0_TT;
    const int tid = threadIdx.x;

    for (int i = tid; i < CC * 10; i += 256) sw[i] = w[i];
    for (int i = tid; i < 5 * C0_TT + 10; i += 256) {
        int gi = 5 * t0 + i;
        sx[i] = (gi < L0) ? x[b * L0 + gi] : 0.0f;
    }
    __syncthreads();

    for (int idx = tid; idx < CC * C0_TT; idx += 256) {
        int tl = idx & (C0_TT - 1);
        int c  = idx >> 7;
        int t  = t0 + tl;
        if (t < T0) {
            float acc = 0.0f;
            const float* wc = &sw[c * 10];
            const float* xp = &sx[5 * tl];
            #pragma unroll
            for (int j = 0; j < 10; ++j) acc = fmaf(wc[j], xp[j], acc);
            out[(b * CC + c) * T0 + t] = acc;
        }
    }
}

// ---------------------------------------------------------------------------
// per-(b,c) norm + affine + gelu -> half parity planes in g_H1
// ---------------------------------------------------------------------------
__global__ __launch_bounds__(256) void gn_gelu_kernel(
    const float* __restrict__ h, const float* __restrict__ scale,
    const float* __restrict__ bias, __half* __restrict__ outH)
{
    const int c = blockIdx.x;
    const int b = blockIdx.y;
    const int tid = threadIdx.x;
    const float* p = h + (size_t)(b * CC + c) * T0;

    float s = 0.0f, s2 = 0.0f;
    for (int i = tid; i < T0; i += 256) {
        float v = p[i];
        s += v; s2 += v * v;
    }
    #pragma unroll
    for (int off = 16; off > 0; off >>= 1) {
        s  += __shfl_down_sync(0xffffffffu, s,  off);
        s2 += __shfl_down_sync(0xffffffffu, s2, off);
    }
    __shared__ float ws[8], ws2[8];
    int wid = tid >> 5, lid = tid & 31;
    if (lid == 0) { ws[wid] = s; ws2[wid] = s2; }
    __syncthreads();
    if (tid == 0) {
        float S = 0.0f, S2 = 0.0f;
        #pragma unroll
        for (int i = 0; i < 8; ++i) { S += ws[i]; S2 += ws2[i]; }
        ws[0] = S; ws2[0] = S2;
    }
    __syncthreads();
    float mean = ws[0] * (1.0f / T0);
    float var  = ws2[0] * (1.0f / T0) - mean * mean;
    float inv  = rsqrtf(var + 1e-5f);
    float a = scale[c] * inv;
    float d = bias[c] - mean * a;

    __half* ob = outH + ((size_t)(b * CC + c) * 2) * HP1;
    for (int i = tid; i < 8008; i += 256) {
        float v = (i < T0) ? gelu_tanh(fmaf(p[i], a, d)) : 0.0f;
        ob[(size_t)(i & 1) * HP1 + (i >> 1)] = __float2half_rn(v);
    }
}

// ---------------------------------------------------------------------------
// Weight prep (all 6 layers, one launch): fp16 + m16n8k16 A-fragment order.
// ---------------------------------------------------------------------------
__global__ __launch_bounds__(256) void wprep_kernel(
    const float* __restrict__ s1, const float* __restrict__ s2,
    const float* __restrict__ s3, const float* __restrict__ s4,
    const float* __restrict__ s5, const float* __restrict__ s6,
    __half* __restrict__ dstAll)
{
    const int ly = blockIdx.y;
    const float* src = (ly == 0) ? s1 : (ly == 1) ? s2 : (ly == 2) ? s3 :
                       (ly == 3) ? s4 : (ly == 4) ? s5 : s6;
    const int K = (ly < 4) ? 3 : 2;
    size_t base = (ly <= 4) ? (size_t)ly * 786432 : (4u * 786432 + 524288);
    __half* dst = dstAll + base;
    const int total = K * 262144;

    for (int d = blockIdx.x * 256 + threadIdx.x; d < total; d += gridDim.x * 256) {
        int hh   = d & 7;
        int lane = (d >> 3) & 31;
        int cb   = (d >> 8) & 31;
        int kc   = (d >> 13) & 31;
        int j    = d >> 18;
        int q = lane >> 2, r4 = lane & 3;
        int ph = hh >> 1, off = hh & 1;
        int m = q + ((ph & 1) ? 8 : 0);
        int k = 2 * r4 + off + ((ph & 2) ? 8 : 0);
        int co = cb * 16 + m;
        int ci = kc * 16 + k;
        dst[d] = __float2half_rn(src[(size_t)(co * 512 + ci) * K + j]);
    }
}

// ---------------------------------------------------------------------------
// fp16 HMMA conv layer. CTA 128co x NT t, 8 warps (2 x 4), warp 64 x NT/4.
// ci-chunks of 16 (one k16 step), 3-stage cp.async pipeline, 16B staging.
// ---------------------------------------------------------------------------
template<int K, int NT, bool F32OUT>
__global__ __launch_bounds__(256, 1) void conv_hmma_kernel(
    const __half* __restrict__ inH, const __half* __restrict__ wh,
    void* __restrict__ outp, int HPin, int HPout, int Tout)
{
    constexpr int NTT  = NT / 32;
    constexpr int WU   = NT + 8;               // plane row halves
    constexpr int ABY  = K * 4096;
    constexpr int PLB  = 16 * WU * 2;
    constexpr int STGB = ABY + K * PLB;
    constexpr int NSB  = NT / 64;              // B 16B-slots per thread (4 / 2)

    extern __shared__ char smem[];

    const int tid = threadIdx.x;
    const int wrp = tid >> 5;
    const int l   = tid & 31;
    const int q   = l >> 2;
    const int r4  = l & 3;
    const int wm  = wrp & 1;
    const int wn  = wrp >> 1;
    const int tw  = wn * (NT / 4);

    const int b   = blockIdx.z;
    const int co0 = blockIdx.y * 128;
    const int cb0 = blockIdx.y * 8;
    const int t0  = blockIdx.x * NT;

    float acc[4][NTT][4];
    #pragma unroll
    for (int mt = 0; mt < 4; ++mt)
        #pragma unroll
        for (int nt = 0; nt < NTT; ++nt)
            #pragma unroll
            for (int e = 0; e < 4; ++e) acc[mt][nt][e] = 0.0f;

    // ---- precomputed staging slots --------------------------------------
    const __half* srcA[K];
    uint32_t dA[K];
    #pragma unroll
    for (int k = 0; k < K; ++k) {
        int i = tid + k * 256;
        int j = i >> 8, x = i & 255;
        dA[k] = j * 4096 + x * 16;
        srcA[k] = wh + (size_t)(j * 32 * 32 + cb0) * 256 + x * 8;
    }
    const __half* srcB[NSB];
    uint32_t dB[NSB];
    #pragma unroll
    for (int k = 0; k < NSB; ++k) {
        int i = tid + k * 256;
        int w, ci, p;
        if (NT == 256) { w = i & 31; ci = (i >> 5) & 15; p = i >> 9; }
        else           { w = i & 15; ci = (i >> 4) & 15; p = i >> 8; }
        dB[k] = ABY + p * PLB + ci * (WU * 2) + w * 16;
        srcB[k] = inH + ((size_t)(b * CC + ci) * 2 + p) * HPin + t0 + 8 * w;
    }
    const __half* srcT = nullptr;
    uint32_t dT = 0;
    if (tid < 32) {
        int p = tid >> 4, ci = tid & 15;
        dT = ABY + p * PLB + ci * (WU * 2) + NT * 2;
        srcT = inH + ((size_t)(b * CC + ci) * 2 + p) * HPin + t0 + NT;
    }

    uint32_t stI = 0;
    auto issue = [&]() {
        char* SB = smem + stI;
        #pragma unroll
        for (int k = 0; k < K; ++k) {
            cp_async16(SB + dA[k], srcA[k]);
            srcA[k] += 8192;
        }
        #pragma unroll
        for (int k = 0; k < NSB; ++k) {
            cp_async16(SB + dB[k], srcB[k]);
            srcB[k] += (size_t)32 * HPin;
        }
        if (tid < 32) {
            cp_async4(SB + dT, srcT);
            srcT += (size_t)32 * HPin;
        }
        cp_commit();
        stI += STGB;
        if (stI == 3 * STGB) stI = 0;
    };

    issue();
    issue();

    const uint32_t smem_base_u = smem_u32(smem);
    uint32_t stC = 0;

    for (int c = 0; c < 32; ++c) {
        if (c < 30)      { issue(); cp_wait<2>(); }
        else if (c == 30) cp_wait<1>();
        else              cp_wait<0>();
        __syncthreads();

        char* SB = smem + stC;
        const uint32_t su = smem_base_u + stC;

        if (K == 3) {
            const uint32_t* p0 = (const uint32_t*)(SB + ABY);
            uint32_t* p2 = (uint32_t*)(SB + ABY + 2 * PLB);
            constexpr int HW = NT / 2;
            #pragma unroll
            for (int k = 0; k < 16 * HW / 256; ++k) {
                int i = tid + k * 256;
                int ci = i / HW;
                int vi = i - ci * HW;
                const uint32_t* row = p0 + ci * (WU / 2);
                uint32_t lo = row[vi], hi = row[vi + 1];
                p2[ci * (WU / 2) + vi] = __funnelshift_r(lo, hi, 16);
            }
            __syncthreads();
        }

        #pragma unroll
        for (int j = 0; j < K; ++j) {
            uint4 af[4];
            #pragma unroll
            for (int mt = 0; mt < 4; ++mt)
                af[mt] = *(const uint4*)(SB + j * 4096 + (wm * 4 + mt) * 512 + l * 16);
            #pragma unroll
            for (int nt = 0; nt < NTT; ++nt) {
                uint32_t b0, b1;
                uint32_t baddr = su + ABY + j * PLB + (l & 15) * (WU * 2)
                               + (tw + 8 * nt) * 2;
                ldmx2t(b0, b1, baddr);
                #pragma unroll
                for (int mt = 0; mt < 4; ++mt)
                    mma_f16(acc[mt][nt], (const uint32_t*)&af[mt], b0, b1);
            }
        }
        __syncthreads();

        stC += STGB;
        if (stC == 3 * STGB) stC = 0;
    }

    // ---- epilogue -------------------------------------------------------
    if (F32OUT) {
        float* ob = (float*)outp;
        #pragma unroll
        for (int mt = 0; mt < 4; ++mt) {
            int row0 = co0 + wm * 64 + 16 * mt + q;
            #pragma unroll
            for (int nt = 0; nt < NTT; ++nt) {
                int t = t0 + tw + 8 * nt + 2 * r4;
                float v0 = gelu_tanh(acc[mt][nt][0]);
                float v1 = gelu_tanh(acc[mt][nt][1]);
                float v2 = gelu_tanh(acc[mt][nt][2]);
                float v3 = gelu_tanh(acc[mt][nt][3]);
                if (t < Tout) {
                    ob[(size_t)(b * CC + row0) * Tout + t]     = v0;
                    ob[(size_t)(b * CC + row0 + 8) * Tout + t] = v2;
                }
                if (t + 1 < Tout) {
                    ob[(size_t)(b * CC + row0) * Tout + t + 1]     = v1;
                    ob[(size_t)(b * CC + row0 + 8) * Tout + t + 1] = v3;
                }
            }
        }
    } else {
        __half* oh = (__half*)outp;
        #pragma unroll
        for (int mt = 0; mt < 4; ++mt) {
            int row0 = co0 + wm * 64 + 16 * mt + q;
            size_t base0 = (size_t)(b * CC + row0) * 2 * HPout;
            size_t base8 = (size_t)(b * CC + row0 + 8) * 2 * HPout;
            #pragma unroll
            for (int nt = 0; nt < NTT; ++nt) {
                int t = t0 + tw + 8 * nt + 2 * r4;
                int u = t >> 1;
                __half h0 = (t     < Tout) ? __float2half_rn(gelu_tanh(acc[mt][nt][0])) : __half(0.0f);
                __half h1 = (t + 1 < Tout) ? __float2half_rn(gelu_tanh(acc[mt][nt][1])) : __half(0.0f);
                __half h2 = (t     < Tout) ? __float2half_rn(gelu_tanh(acc[mt][nt][2])) : __half(0.0f);
                __half h3 = (t + 1 < Tout) ? __float2half_rn(gelu_tanh(acc[mt][nt][3])) : __half(0.0f);
                oh[base0 + u]         = h0;
                oh[base0 + HPout + u] = h1;
                oh[base8 + u]         = h2;
                oh[base8 + HPout + u] = h3;
            }
        }
    }
}

// ---------------------------------------------------------------------------
// Tail head (reads fp32 conv6 output)
// ---------------------------------------------------------------------------
__global__ __launch_bounds__(256) void tail_kernel(
    const float* __restrict__ h, const int* __restrict__ word_ids,
    const float* __restrict__ proj_w, const float* __restrict__ proj_b,
    const float* __restrict__ cls_w1, const float* __restrict__ cls_b1,
    const float* __restrict__ cls_w2, const float* __restrict__ cls_b2,
    float* __restrict__ out)
{
    const int b = blockIdx.x;
    const int tid = threadIdx.x;
    __shared__ float feat[CC];
    __shared__ float pr[256];
    __shared__ float h1[128];

    const float* hb = h + (size_t)b * CC * T6;
    for (int c = tid; c < CC; c += 256) {
        float s = 0.0f;
        const float* row = hb + (size_t)c * T6;
        for (int t = 0; t < T6; ++t) s += row[t];
        feat[c] = s * (1.0f / (float)T6);
    }
    __syncthreads();

    {
        float s = proj_b[tid];
        const float* wrow = proj_w + (size_t)tid * CC;
        for (int d = 0; d < CC; ++d) s = fmaf(wrow[d], feat[d], s);
        pr[tid] = fmaxf(s, 0.0f);
    }
    __syncthreads();

    const int wd = word_ids[b];
    if (tid < 128) {
        float s = cls_b1[wd * 128 + tid];
        const float* w1 = cls_w1 + (size_t)wd * 256 * 128;
        for (int d = 0; d < 256; ++d)
            s = fmaf(pr[d], w1[d * 128 + tid], s);
        h1[tid] = fmaxf(s, 0.0f);
    }
    __syncthreads();

    if (tid < 5) {
        float s = cls_b2[wd * 5 + tid];
        const float* w2 = cls_w2 + (size_t)wd * 128 * 5;
        for (int d = 0; d < 128; ++d)
            s = fmaf(h1[d], w2[d * 5 + tid], s);
        out[b * 5 + tid] = s;
    }
}

// ---------------------------------------------------------------------------
// Launch
// ---------------------------------------------------------------------------
extern "C" void kernel_launch(void* const* d_in, const int* in_sizes, int n_in,
                              void* d_out, int out_size)
{
    const float* x        = (const float*)d_in[0];
    const int*   word_ids = (const int*)  d_in[1];
    const float* gn_scale = (const float*)d_in[2];
    const float* gn_bias  = (const float*)d_in[3];
    const float* proj_w   = (const float*)d_in[4];
    const float* proj_b   = (const float*)d_in[5];
    const float* cls_w1   = (const float*)d_in[6];
    const float* cls_b1   = (const float*)d_in[7];
    const float* cls_w2   = (const float*)d_in[8];
    const float* cls_b2   = (const float*)d_in[9];
    const float* w0       = (const float*)d_in[10];
    const float* w1       = (const float*)d_in[11];
    const float* w2       = (const float*)d_in[12];
    const float* w3       = (const float*)d_in[13];
    const float* w4       = (const float*)d_in[14];
    const float* w5       = (const float*)d_in[15];
    const float* w6       = (const float*)d_in[16];
    float* out = (float*)d_out;

    float *bufA = nullptr;
    __half *H1 = nullptr, *H2 = nullptr, *wrh = nullptr;
    cudaGetSymbolAddress((void**)&bufA, g_bufA);
    cudaGetSymbolAddress((void**)&H1, g_H1);
    cudaGetSymbolAddress((void**)&H2, g_H2);
    cudaGetSymbolAddress((void**)&wrh, g_wrh);

    const size_t PL3 = 786432;
    __half* wr1 = wrh;
    __half* wr2 = wr1 + PL3;
    __half* wr3 = wr2 + PL3;
    __half* wr4 = wr3 + PL3;
    __half* wr5 = wr4 + PL3;
    __half* wr6 = wr5 + 524288;

    // 3-stage smem: 3 * (K*4096 + K*16*(NT+8)*2)
    const int SM3_256 = 3 * (3 * 4096 + 3 * 16 * 264 * 2);   // 112896
    const int SM3_128 = 3 * (3 * 4096 + 3 * 16 * 136 * 2);   // 76032
    const int SM2_128 = 3 * (2 * 4096 + 2 * 16 * 136 * 2);   // 50688
    cudaFuncSetAttribute((const void*)conv_hmma_kernel<3, 256, false>,
                         cudaFuncAttributeMaxDynamicSharedMemorySize, SM3_256);
    cudaFuncSetAttribute((const void*)conv_hmma_kernel<3, 128, false>,
                         cudaFuncAttributeMaxDynamicSharedMemorySize, SM3_128);
    cudaFuncSetAttribute((const void*)conv_hmma_kernel<2, 128, false>,
                         cudaFuncAttributeMaxDynamicSharedMemorySize, SM2_128);
    cudaFuncSetAttribute((const void*)conv_hmma_kernel<2, 128, true>,
                         cudaFuncAttributeMaxDynamicSharedMemorySize, SM2_128);

    wprep_kernel<<<dim3(96, 6), 256>>>(w1, w2, w3, w4, w5, w6, wrh);
    conv0_kernel<<<dim3((T0 + C0_TT - 1) / C0_TT, BB), 256>>>(x, w0, bufA);
    gn_gelu_kernel<<<dim3(CC, BB), 256>>>(bufA, gn_scale, gn_bias, H1);

    conv_hmma_kernel<3, 256, false><<<dim3(16, 4, BB), 256, SM3_256>>>(
        H1, wr1, H2, HP1, HP2, T1);
    conv_hmma_kernel<3, 256, false><<<dim3(8, 4, BB), 256, SM3_256>>>(
        H2, wr2, H1, HP2, HP1, T2);
    conv_hmma_kernel<3, 256, false><<<dim3(4, 4, BB), 256, SM3_256>>>(
        H1, wr3, H2, HP1, HP2, T3);
    conv_hmma_kernel<3, 128, false><<<dim3(4, 4, BB), 256, SM3_128>>>(
        H2, wr4, H1, HP2, HP1, T4);
    conv_hmma_kernel<2, 128, false><<<dim3(2, 4, BB), 256, SM2_128>>>(
        H1, wr5, H2, HP1, HP2, T5);
    conv_hmma_kernel<2, 128, true><<<dim3(1, 4, BB), 256, SM2_128>>>(
        H2, wr6, bufA, HP2, 0, T6);

    tail_kernel<<<BB, 256>>>(bufA, word_ids, proj_w, proj_b,
                             cls_w1, cls_b1, cls_w2, cls_b2, out);
}